// round 1
// baseline (speedup 1.0000x reference)
#include <cuda_runtime.h>
#include <math.h>

// Problem dims (fixed by the dataset)
#define BB   4
#define SS   2048
#define DD   1024
#define HH   16
#define HD   64
#define DFF  4096
#define ROWS (BB*SS)   // 8192

// ---------------- scratch (static device globals; no allocation) -----------
__device__ float g_h  [ (size_t)ROWS*DD ];   // LN output (reused for LN2)
__device__ float g_q  [ (size_t)ROWS*DD ];
__device__ float g_k  [ (size_t)ROWS*DD ];
__device__ float g_v  [ (size_t)ROWS*DD ];
__device__ float g_ctx[ (size_t)ROWS*DD ];
__device__ float g_x1 [ (size_t)ROWS*DD ];
__device__ float g_ff [ (size_t)ROWS*DFF ];

// ---------------- LayerNorm: one block per row ------------------------------
__global__ __launch_bounds__(256)
void ln_kernel(const float* __restrict__ x, const float* __restrict__ scale,
               const float* __restrict__ shift, float* __restrict__ out)
{
    int row = blockIdx.x;
    const float* xr = x + (size_t)row * DD;
    float*       orow = out + (size_t)row * DD;
    int t = threadIdx.x;

    float v0 = xr[t], v1 = xr[t+256], v2 = xr[t+512], v3 = xr[t+768];
    float s  = v0+v1+v2+v3;
    float sq = v0*v0+v1*v1+v2*v2+v3*v3;

    __shared__ float red[2][256];
    red[0][t]=s; red[1][t]=sq; __syncthreads();
    for (int off=128; off>0; off>>=1) {
        if (t<off){ red[0][t]+=red[0][t+off]; red[1][t]+=red[1][t+off]; }
        __syncthreads();
    }
    float mean = red[0][0] * (1.0f/DD);
    float var  = red[1][0] * (1.0f/DD) - mean*mean;
    float inv  = rsqrtf(var + 1e-8f);

    orow[t    ] = scale[t    ]*(v0-mean)*inv + shift[t    ];
    orow[t+256] = scale[t+256]*(v1-mean)*inv + shift[t+256];
    orow[t+512] = scale[t+512]*(v2-mean)*inv + shift[t+512];
    orow[t+768] = scale[t+768]*(v3-mean)*inv + shift[t+768];
}

// ---------------- SGEMM 128x128x8, 256 threads, 8x8 microtile ---------------
// EPI: 0 = C = A@B
//      1 = C = res + A@B + bias          (bias per-column)
//      2 = C = gelu(A@B + bias)
__device__ __forceinline__ float gelu_f(float x) {
    float u = 0.7978845608028654f * (x + 0.044715f * x * x * x);
    return 0.5f * x * (1.0f + tanhf(u));
}

template<int EPI>
__global__ __launch_bounds__(256)
void sgemm(const float* __restrict__ A, const float* __restrict__ Bm,
           const float* __restrict__ bias, const float* __restrict__ res,
           float* __restrict__ C, int M, int N, int K)
{
    constexpr int BM=128, BN=128, BK=8;
    __shared__ float As[BK][BM];
    __shared__ float Bs[BK][BN];

    int tid  = threadIdx.x;
    int brow = blockIdx.y * BM;
    int bcol = blockIdx.x * BN;
    int ty = tid >> 4, tx = tid & 15;

    float acc[8][8];
    #pragma unroll
    for (int i=0;i<8;i++)
        #pragma unroll
        for (int j=0;j<8;j++) acc[i][j]=0.f;

    int ar = tid >> 1,  ac = (tid & 1) * 4;   // A tile 128x8 : 1 float4/thread
    int br = tid >> 5,  bc = (tid & 31) * 4;  // B tile 8x128 : 1 float4/thread
    const float* Aptr = A + (size_t)(brow + ar) * K + ac;
    const float* Bbase = Bm + (size_t)br * N + bcol + bc;

    for (int k0=0; k0<K; k0+=BK) {
        float4 av = *(const float4*)Aptr;  Aptr += BK;
        float4 bv = *(const float4*)(Bbase + (size_t)k0 * N);
        As[ac+0][ar]=av.x; As[ac+1][ar]=av.y; As[ac+2][ar]=av.z; As[ac+3][ar]=av.w;
        *(float4*)&Bs[br][bc] = bv;
        __syncthreads();

        #pragma unroll
        for (int k=0;k<BK;k++) {
            float a[8], b[8];
            #pragma unroll
            for (int i=0;i<8;i++) a[i] = As[k][ty*8+i];
            #pragma unroll
            for (int j=0;j<8;j++) b[j] = Bs[k][tx*8+j];
            #pragma unroll
            for (int i=0;i<8;i++)
                #pragma unroll
                for (int j=0;j<8;j++)
                    acc[i][j] += a[i]*b[j];
        }
        __syncthreads();
    }

    #pragma unroll
    for (int i=0;i<8;i++) {
        int r = brow + ty*8 + i;
        size_t roff = (size_t)r * N;
        #pragma unroll
        for (int j=0;j<8;j++) {
            int c = bcol + tx*8 + j;
            float v = acc[i][j];
            if (EPI==1) v = v + bias[c] + res[roff + c];
            if (EPI==2) v = gelu_f(v + bias[c]);
            C[roff + c] = v;
        }
    }
}

// ---------------- causal flash attention ------------------------------------
// grid = (S/128, B*H), block = 128 threads; thread t owns query row qt*128+t.
// K/V tiles of 64 keys staged in smem; online softmax in 16-key chunks.
__global__ __launch_bounds__(128)
void attn_kernel(const float* __restrict__ Q, const float* __restrict__ K,
                 const float* __restrict__ V, float* __restrict__ O)
{
    constexpr int QB=128, KB=64;
    constexpr float SCALE = 0.125f; // 1/sqrt(64)

    int qt = blockIdx.x;
    int bh = blockIdx.y;
    int b  = bh / HH;
    int h  = bh % HH;
    int t  = threadIdx.x;
    int q  = qt*QB + t;

    const float* Qrow = Q + ((size_t)(b*SS + q))*DD + h*HD;
    float qreg[HD];
    #pragma unroll
    for (int d=0; d<HD; d+=4) {
        float4 v4 = *(const float4*)&Qrow[d];
        qreg[d]=v4.x; qreg[d+1]=v4.y; qreg[d+2]=v4.z; qreg[d+3]=v4.w;
    }

    float o[HD];
    #pragma unroll
    for (int d=0; d<HD; d++) o[d]=0.f;
    float m = -INFINITY, l = 0.f;

    __shared__ float Ks[KB][HD];
    __shared__ float Vs[KB][HD];

    int nk = qt*QB + QB;  // keys [0, nk) cover causal range for all rows in block
    for (int k0=0; k0<nk; k0+=KB) {
        __syncthreads();
        // stage K/V tile: 1024 float4 slots each, 128 threads -> 8 iters
        for (int i=t; i<KB*(HD/4); i+=128) {
            int row = i >> 4, col = (i & 15) * 4;
            size_t g = ((size_t)(b*SS + k0 + row))*DD + h*HD + col;
            *(float4*)&Ks[row][col] = *(const float4*)&K[g];
            *(float4*)&Vs[row][col] = *(const float4*)&V[g];
        }
        __syncthreads();

        for (int c0=0; c0<KB; c0+=16) {
            float s[16];
            #pragma unroll
            for (int j=0;j<16;j++) {
                float acc = 0.f;
                #pragma unroll
                for (int d=0; d<HD; d++) acc += qreg[d] * Ks[c0+j][d];
                int key = k0 + c0 + j;
                s[j] = (key <= q) ? acc * SCALE : -INFINITY;
            }
            float cmax = m;
            #pragma unroll
            for (int j=0;j<16;j++) cmax = fmaxf(cmax, s[j]);
            float corr = __expf(m - cmax);   // 0 when m==-inf, cmax finite
            m = cmax;
            l *= corr;
            #pragma unroll
            for (int d=0; d<HD; d++) o[d] *= corr;
            #pragma unroll
            for (int j=0;j<16;j++) {
                float p = __expf(s[j] - m);  // 0 for masked keys
                l += p;
                #pragma unroll
                for (int d=0; d<HD; d++) o[d] += p * Vs[c0+j][d];
            }
        }
    }

    float inv = 1.0f / l;
    float* Orow = O + ((size_t)(b*SS + q))*DD + h*HD;
    #pragma unroll
    for (int d=0; d<HD; d+=4) {
        float4 v4;
        v4.x=o[d]*inv; v4.y=o[d+1]*inv; v4.z=o[d+2]*inv; v4.w=o[d+3]*inv;
        *(float4*)&Orow[d] = v4;
    }
}

// ---------------- launcher ---------------------------------------------------
extern "C" void kernel_launch(void* const* d_in, const int* in_sizes, int n_in,
                              void* d_out, int out_size)
{
    const float* x    = (const float*)d_in[0];
    const float* Wq   = (const float*)d_in[1];
    const float* Wk   = (const float*)d_in[2];
    const float* Wv   = (const float*)d_in[3];
    const float* Wo   = (const float*)d_in[4];
    const float* bo   = (const float*)d_in[5];
    const float* W1   = (const float*)d_in[6];
    const float* b1   = (const float*)d_in[7];
    const float* W2   = (const float*)d_in[8];
    const float* b2   = (const float*)d_in[9];
    const float* ln1s = (const float*)d_in[10];
    const float* ln1b = (const float*)d_in[11];
    const float* ln2s = (const float*)d_in[12];
    const float* ln2b = (const float*)d_in[13];
    float* out = (float*)d_out;

    float *h,*q,*k,*v,*ctx,*x1,*ff;
    cudaGetSymbolAddress((void**)&h,   g_h);
    cudaGetSymbolAddress((void**)&q,   g_q);
    cudaGetSymbolAddress((void**)&k,   g_k);
    cudaGetSymbolAddress((void**)&v,   g_v);
    cudaGetSymbolAddress((void**)&ctx, g_ctx);
    cudaGetSymbolAddress((void**)&x1,  g_x1);
    cudaGetSymbolAddress((void**)&ff,  g_ff);

    dim3 gD (DD/128,  ROWS/128);   // N=1024 GEMMs
    dim3 gFF(DFF/128, ROWS/128);   // N=4096 GEMM

    // 1. LN1
    ln_kernel<<<ROWS, 256>>>(x, ln1s, ln1b, h);
    // 2-4. QKV projections
    sgemm<0><<<gD, 256>>>(h, Wq, nullptr, nullptr, q, ROWS, DD, DD);
    sgemm<0><<<gD, 256>>>(h, Wk, nullptr, nullptr, k, ROWS, DD, DD);
    sgemm<0><<<gD, 256>>>(h, Wv, nullptr, nullptr, v, ROWS, DD, DD);
    // 5. causal attention
    attn_kernel<<<dim3(SS/128, BB*HH), 128>>>(q, k, v, ctx);
    // 6. output projection + bias + residual
    sgemm<1><<<gD, 256>>>(ctx, Wo, bo, x, x1, ROWS, DD, DD);
    // 7. LN2
    ln_kernel<<<ROWS, 256>>>(x1, ln2s, ln2b, h);
    // 8. FFN up + GELU
    sgemm<2><<<gFF, 256>>>(h, W1, b1, nullptr, ff, ROWS, DFF, DD);
    // 9. FFN down + bias + residual
    sgemm<1><<<gD, 256>>>(ff, W2, b2, x1, out, ROWS, DD, DFF);
}

// round 3
// speedup vs baseline: 1.3235x; 1.3235x over previous
#include <cuda_runtime.h>
#include <math.h>
#include <stdint.h>

typedef unsigned long long ull;

#define BB   4
#define SS   2048
#define DD   1024
#define HH   16
#define HD   64
#define DFF  4096
#define ROWS (BB*SS)   // 8192

// ---------------- scratch (static device globals; no allocation) -----------
__device__ float g_h  [ (size_t)ROWS*DD ];
__device__ float g_q  [ (size_t)ROWS*DD ];
__device__ float g_k  [ (size_t)ROWS*DD ];
__device__ float g_v  [ (size_t)ROWS*DD ];
__device__ float g_ctx[ (size_t)ROWS*DD ];
__device__ float g_x1 [ (size_t)ROWS*DD ];
__device__ float g_ff [ (size_t)ROWS*DFF ];

// packed f32x2 ops
#define FMA2(d,a,b,c) asm("fma.rn.f32x2 %0, %1, %2, %3;" : "=l"(d) : "l"(a), "l"(b), "l"(c))
#define MUL2(d,a,b)   asm("mul.rn.f32x2 %0, %1, %2;" : "=l"(d) : "l"(a), "l"(b))
#define PK2(d,lo,hi)  asm("mov.b64 %0, {%1, %2};" : "=l"(d) : "f"(lo), "f"(hi))
#define UPK2(lo,hi,s) asm("mov.b64 {%0, %1}, %2;" : "=f"(lo), "=f"(hi) : "l"(s))

__device__ __forceinline__ uint32_t f2tf32(float v) {
    uint32_t u;
    asm("cvt.rna.tf32.f32 %0, %1;" : "=r"(u) : "f"(v));
    return u;
}

// ======================= LayerNorm ==========================================
__global__ __launch_bounds__(256)
void ln_kernel(const float* __restrict__ x, const float* __restrict__ scale,
               const float* __restrict__ shift, float* __restrict__ out)
{
    int row = blockIdx.x;
    const float* xr = x + (size_t)row * DD;
    float* orow = out + (size_t)row * DD;
    int t = threadIdx.x;

    float v0 = xr[t], v1 = xr[t+256], v2 = xr[t+512], v3 = xr[t+768];
    float s  = v0+v1+v2+v3;
    float sq = v0*v0+v1*v1+v2*v2+v3*v3;

    __shared__ float red[2][256];
    red[0][t]=s; red[1][t]=sq; __syncthreads();
    for (int off=128; off>0; off>>=1) {
        if (t<off){ red[0][t]+=red[0][t+off]; red[1][t]+=red[1][t+off]; }
        __syncthreads();
    }
    float mean = red[0][0] * (1.0f/DD);
    float var  = red[1][0] * (1.0f/DD) - mean*mean;
    float inv  = rsqrtf(var + 1e-8f);

    orow[t    ] = scale[t    ]*(v0-mean)*inv + shift[t    ];
    orow[t+256] = scale[t+256]*(v1-mean)*inv + shift[t+256];
    orow[t+512] = scale[t+512]*(v2-mean)*inv + shift[t+512];
    orow[t+768] = scale[t+768]*(v3-mean)*inv + shift[t+768];
}

// ======================= tf32 mma.sync GEMM =================================
// C[M,N] = A[M,K] @ W[K,N]   (W consumed directly, k-major = B fragment layout)
// 128 threads = 4 warps, block tile 128x128, warp tile 64x64, BK=32.
// EPI: 0 plain, 1 bias+residual, 2 gelu(bias)
__device__ __forceinline__ float gelu_f(float x) {
    float u = 0.7978845608028654f * (x + 0.044715f * x * x * x);
    return 0.5f * x * (1.0f + tanhf(u));
}

#define ASTRIDE 36
#define BSTRIDE 132

template<int EPI>
__global__ __launch_bounds__(128)
void tgemm(const float* __restrict__ A, const float* __restrict__ W,
           const float* __restrict__ bias, const float* __restrict__ res,
           float* __restrict__ C, int N, int K)
{
    __shared__ float As[128][ASTRIDE];   // [m][k] tf32 bits
    __shared__ float Bs[32][BSTRIDE];    // [k][n] tf32 bits

    const int tid = threadIdx.x;
    const int wid = tid >> 5, lane = tid & 31;
    const int g = lane >> 2, tg = lane & 3;
    const int wm = (wid >> 1) * 64;      // warp m offset
    const int wn = (wid & 1) * 64;       // warp n offset

    const int brow = blockIdx.y * 128, bcol = blockIdx.x * 128;

    float acc[4][8][4];
    #pragma unroll
    for (int mi=0;mi<4;mi++)
        #pragma unroll
        for (int ni=0;ni<8;ni++)
            #pragma unroll
            for (int e=0;e<4;e++) acc[mi][ni][e]=0.f;

    for (int k0 = 0; k0 < K; k0 += 32) {
        __syncthreads();
        // stage A: 128 rows x 32 cols; iter idx -> row=idx>>3, c4=idx&7
        #pragma unroll
        for (int it = 0; it < 8; it++) {
            int idx = it * 128 + tid;
            int row = idx >> 3, c4 = (idx & 7) * 4;
            float4 v = *(const float4*)(A + (size_t)(brow + row) * K + k0 + c4);
            As[row][c4+0] = __uint_as_float(f2tf32(v.x));
            As[row][c4+1] = __uint_as_float(f2tf32(v.y));
            As[row][c4+2] = __uint_as_float(f2tf32(v.z));
            As[row][c4+3] = __uint_as_float(f2tf32(v.w));
        }
        // stage B: 32 rows x 128 cols; iter idx -> row=idx>>5, c4=idx&31
        #pragma unroll
        for (int it = 0; it < 8; it++) {
            int idx = it * 128 + tid;
            int row = idx >> 5, c4 = (idx & 31) * 4;
            float4 v = *(const float4*)(W + (size_t)(k0 + row) * N + bcol + c4);
            Bs[row][c4+0] = __uint_as_float(f2tf32(v.x));
            Bs[row][c4+1] = __uint_as_float(f2tf32(v.y));
            Bs[row][c4+2] = __uint_as_float(f2tf32(v.z));
            Bs[row][c4+3] = __uint_as_float(f2tf32(v.w));
        }
        __syncthreads();

        #pragma unroll
        for (int kk = 0; kk < 32; kk += 8) {
            uint32_t af[4][4];
            #pragma unroll
            for (int mi = 0; mi < 4; mi++) {
                int r0 = wm + mi*16 + g;
                af[mi][0] = __float_as_uint(As[r0    ][kk + tg    ]);
                af[mi][1] = __float_as_uint(As[r0 + 8][kk + tg    ]);
                af[mi][2] = __float_as_uint(As[r0    ][kk + tg + 4]);
                af[mi][3] = __float_as_uint(As[r0 + 8][kk + tg + 4]);
            }
            uint32_t bf[8][2];
            #pragma unroll
            for (int ni = 0; ni < 8; ni++) {
                int c = wn + ni*8 + g;
                bf[ni][0] = __float_as_uint(Bs[kk + tg    ][c]);
                bf[ni][1] = __float_as_uint(Bs[kk + tg + 4][c]);
            }
            #pragma unroll
            for (int mi = 0; mi < 4; mi++)
                #pragma unroll
                for (int ni = 0; ni < 8; ni++) {
                    asm volatile(
                        "mma.sync.aligned.m16n8k8.row.col.f32.tf32.tf32.f32 "
                        "{%0,%1,%2,%3}, {%4,%5,%6,%7}, {%8,%9}, {%0,%1,%2,%3};"
                        : "+f"(acc[mi][ni][0]), "+f"(acc[mi][ni][1]),
                          "+f"(acc[mi][ni][2]), "+f"(acc[mi][ni][3])
                        : "r"(af[mi][0]), "r"(af[mi][1]), "r"(af[mi][2]), "r"(af[mi][3]),
                          "r"(bf[ni][0]), "r"(bf[ni][1]));
                }
        }
    }

    // epilogue: c0,c1 at (row, 2tg..2tg+1), c2,c3 at (row+8, same cols)
    #pragma unroll
    for (int mi = 0; mi < 4; mi++) {
        int r0 = brow + wm + mi*16 + g;
        #pragma unroll
        for (int ni = 0; ni < 8; ni++) {
            int c = bcol + wn + ni*8 + 2*tg;
            float v0 = acc[mi][ni][0], v1 = acc[mi][ni][1];
            float v2 = acc[mi][ni][2], v3 = acc[mi][ni][3];
            if (EPI == 1) {
                float b0 = bias[c], b1 = bias[c+1];
                const float* R0 = res + (size_t)r0 * N + c;
                const float* R1 = res + (size_t)(r0+8) * N + c;
                v0 += b0 + R0[0]; v1 += b1 + R0[1];
                v2 += b0 + R1[0]; v3 += b1 + R1[1];
            }
            if (EPI == 2) {
                float b0 = bias[c], b1 = bias[c+1];
                v0 = gelu_f(v0 + b0); v1 = gelu_f(v1 + b1);
                v2 = gelu_f(v2 + b0); v3 = gelu_f(v3 + b1);
            }
            float2 p0 = make_float2(v0, v1);
            float2 p1 = make_float2(v2, v3);
            *(float2*)(C + (size_t)r0 * N + c)     = p0;
            *(float2*)(C + (size_t)(r0+8) * N + c) = p1;
        }
    }
}

// ======================= causal flash attention (f32x2 packed) ==============
__global__ __launch_bounds__(128)
void attn_kernel(const float* __restrict__ Q, const float* __restrict__ K,
                 const float* __restrict__ V, float* __restrict__ O)
{
    constexpr int QB = 128, KB = 64;
    constexpr float SCALE = 0.125f;

    int qt = blockIdx.x;
    int bh = blockIdx.y;
    int b  = bh / HH;
    int h  = bh % HH;
    int t  = threadIdx.x;
    int q  = qt * QB + t;

    const float* Qrow = Q + ((size_t)(b*SS + q))*DD + h*HD;
    float qf[HD];
    #pragma unroll
    for (int d = 0; d < HD; d += 4) {
        float4 v4 = *(const float4*)&Qrow[d];
        qf[d]=v4.x; qf[d+1]=v4.y; qf[d+2]=v4.z; qf[d+3]=v4.w;
    }
    ull q2[HD/2];
    #pragma unroll
    for (int i = 0; i < HD/2; i++) PK2(q2[i], qf[2*i], qf[2*i+1]);

    ull o2[HD/2];
    #pragma unroll
    for (int i = 0; i < HD/2; i++) o2[i] = 0ull;
    float m = -INFINITY, l = 0.f;

    __shared__ float Ks[KB][HD];
    __shared__ float Vs[KB][HD];

    int nk = qt*QB + QB;
    for (int k0 = 0; k0 < nk; k0 += KB) {
        __syncthreads();
        for (int i = t; i < KB*(HD/4); i += 128) {
            int row = i >> 4, col = (i & 15) * 4;
            size_t gidx = ((size_t)(b*SS + k0 + row))*DD + h*HD + col;
            *(float4*)&Ks[row][col] = *(const float4*)&K[gidx];
            *(float4*)&Vs[row][col] = *(const float4*)&V[gidx];
        }
        __syncthreads();

        for (int c0 = 0; c0 < KB; c0 += 16) {
            float s[16];
            #pragma unroll
            for (int j = 0; j < 16; j++) {
                ull acc = 0ull;
                const ull* kp = (const ull*)&Ks[c0+j][0];
                #pragma unroll
                for (int d2 = 0; d2 < HD/2; d2++) FMA2(acc, q2[d2], kp[d2], acc);
                float lo, hi; UPK2(lo, hi, acc);
                int key = k0 + c0 + j;
                s[j] = (key <= q) ? (lo + hi) * SCALE : -INFINITY;
            }
            float cmax = m;
            #pragma unroll
            for (int j = 0; j < 16; j++) cmax = fmaxf(cmax, s[j]);
            float corr = __expf(m - cmax);
            m = cmax;
            l *= corr;
            ull corr2; PK2(corr2, corr, corr);
            #pragma unroll
            for (int i = 0; i < HD/2; i++) MUL2(o2[i], o2[i], corr2);
            #pragma unroll
            for (int j = 0; j < 16; j++) {
                float p = __expf(s[j] - m);
                l += p;
                ull p2; PK2(p2, p, p);
                const ull* vp = (const ull*)&Vs[c0+j][0];
                #pragma unroll
                for (int d2 = 0; d2 < HD/2; d2++) FMA2(o2[d2], p2, vp[d2], o2[d2]);
            }
        }
    }

    float inv = 1.0f / l;
    float* Orow = O + ((size_t)(b*SS + q))*DD + h*HD;
    #pragma unroll
    for (int i = 0; i < HD/2; i++) {
        float lo, hi; UPK2(lo, hi, o2[i]);
        Orow[2*i]   = lo * inv;
        Orow[2*i+1] = hi * inv;
    }
}

// ======================= launcher ===========================================
extern "C" void kernel_launch(void* const* d_in, const int* in_sizes, int n_in,
                              void* d_out, int out_size)
{
    const float* x    = (const float*)d_in[0];
    const float* Wq   = (const float*)d_in[1];
    const float* Wk   = (const float*)d_in[2];
    const float* Wv   = (const float*)d_in[3];
    const float* Wo   = (const float*)d_in[4];
    const float* bo   = (const float*)d_in[5];
    const float* W1   = (const float*)d_in[6];
    const float* b1   = (const float*)d_in[7];
    const float* W2   = (const float*)d_in[8];
    const float* b2   = (const float*)d_in[9];
    const float* ln1s = (const float*)d_in[10];
    const float* ln1b = (const float*)d_in[11];
    const float* ln2s = (const float*)d_in[12];
    const float* ln2b = (const float*)d_in[13];
    float* out = (float*)d_out;

    float *h,*q,*k,*v,*ctx,*x1,*ff;
    cudaGetSymbolAddress((void**)&h,   g_h);
    cudaGetSymbolAddress((void**)&q,   g_q);
    cudaGetSymbolAddress((void**)&k,   g_k);
    cudaGetSymbolAddress((void**)&v,   g_v);
    cudaGetSymbolAddress((void**)&ctx, g_ctx);
    cudaGetSymbolAddress((void**)&x1,  g_x1);
    cudaGetSymbolAddress((void**)&ff,  g_ff);

    dim3 gD (DD/128,  ROWS/128);   // (8, 64)
    dim3 gFF(DFF/128, ROWS/128);   // (32, 64)

    ln_kernel<<<ROWS, 256>>>(x, ln1s, ln1b, h);
    tgemm<0><<<gD, 128>>>(h, Wq, nullptr, nullptr, q, DD, DD);
    tgemm<0><<<gD, 128>>>(h, Wk, nullptr, nullptr, k, DD, DD);
    tgemm<0><<<gD, 128>>>(h, Wv, nullptr, nullptr, v, DD, DD);
    attn_kernel<<<dim3(SS/128, BB*HH), 128>>>(q, k, v, ctx);
    tgemm<1><<<gD, 128>>>(ctx, Wo, bo, x, x1, DD, DD);
    ln_kernel<<<ROWS, 256>>>(x1, ln2s, ln2b, h);
    tgemm<2><<<gFF, 128>>>(h, W1, b1, nullptr, ff, DFF, DD);
    tgemm<1><<<gD, 128>>>(ff, W2, b2, x1, out, DD, DFF);
}

// round 4
// speedup vs baseline: 4.0040x; 3.0254x over previous
#include <cuda_runtime.h>
#include <math.h>
#include <stdint.h>

#define BB   4
#define SS   2048
#define DD   1024
#define HH   16
#define HD   64
#define DFF  4096
#define ROWS (BB*SS)   // 8192

// ---------------- scratch (static device globals; no allocation) -----------
__device__ float g_h  [ (size_t)ROWS*DD ];
__device__ float g_q  [ (size_t)ROWS*DD ];
__device__ float g_k  [ (size_t)ROWS*DD ];
__device__ float g_v  [ (size_t)ROWS*DD ];
__device__ float g_ctx[ (size_t)ROWS*DD ];
__device__ float g_x1 [ (size_t)ROWS*DD ];
__device__ float g_ff [ (size_t)ROWS*DFF ];
// tf32-rounded weight copies (native [K,N] layout)
__device__ float g_wq[ (size_t)DD*DD ];
__device__ float g_wk[ (size_t)DD*DD ];
__device__ float g_wv[ (size_t)DD*DD ];
__device__ float g_wo[ (size_t)DD*DD ];
__device__ float g_w1[ (size_t)DD*DFF ];
__device__ float g_w2[ (size_t)DFF*DD ];

__device__ __forceinline__ float f2tf32f(float v) {
    uint32_t u;
    asm("cvt.rna.tf32.f32 %0, %1;" : "=r"(u) : "f"(v));
    return __uint_as_float(u);
}
__device__ __forceinline__ uint32_t smem_u32(const void* p) {
    uint32_t a;
    asm("{ .reg .u64 t; cvta.to.shared.u64 t, %1; cvt.u32.u64 %0, t; }" : "=r"(a) : "l"(p));
    return a;
}
__device__ __forceinline__ void cp_async16(uint32_t dst, const void* src) {
    asm volatile("cp.async.cg.shared.global [%0], [%1], 16;" :: "r"(dst), "l"(src));
}
#define CP_COMMIT() asm volatile("cp.async.commit_group;")
#define CP_WAIT(N)  asm volatile("cp.async.wait_group %0;" :: "n"(N))

#define MMA_TF32(acc, a0,a1,a2,a3, b0,b1) \
    asm volatile("mma.sync.aligned.m16n8k8.row.col.f32.tf32.tf32.f32 " \
        "{%0,%1,%2,%3}, {%4,%5,%6,%7}, {%8,%9}, {%0,%1,%2,%3};" \
        : "+f"((acc)[0]), "+f"((acc)[1]), "+f"((acc)[2]), "+f"((acc)[3]) \
        : "r"(a0), "r"(a1), "r"(a2), "r"(a3), "r"(b0), "r"(b1))

// ======================= tf32 weight conversion =============================
__global__ __launch_bounds__(256)
void cvt_tf32_kernel(const float* __restrict__ in, float* __restrict__ out, int n4)
{
    int i = blockIdx.x * 256 + threadIdx.x;
    if (i < n4) {
        float4 v = ((const float4*)in)[i];
        v.x = f2tf32f(v.x); v.y = f2tf32f(v.y);
        v.z = f2tf32f(v.z); v.w = f2tf32f(v.w);
        ((float4*)out)[i] = v;
    }
}

// ======================= LayerNorm (emits tf32-rounded) =====================
__global__ __launch_bounds__(256)
void ln_kernel(const float* __restrict__ x, const float* __restrict__ scale,
               const float* __restrict__ shift, float* __restrict__ out)
{
    int row = blockIdx.x;
    const float* xr = x + (size_t)row * DD;
    float* orow = out + (size_t)row * DD;
    int t = threadIdx.x;

    float v0 = xr[t], v1 = xr[t+256], v2 = xr[t+512], v3 = xr[t+768];
    float s  = v0+v1+v2+v3;
    float sq = v0*v0+v1*v1+v2*v2+v3*v3;

    __shared__ float red[2][256];
    red[0][t]=s; red[1][t]=sq; __syncthreads();
    for (int off=128; off>0; off>>=1) {
        if (t<off){ red[0][t]+=red[0][t+off]; red[1][t]+=red[1][t+off]; }
        __syncthreads();
    }
    float mean = red[0][0] * (1.0f/DD);
    float var  = red[1][0] * (1.0f/DD) - mean*mean;
    float inv  = rsqrtf(var + 1e-8f);

    orow[t    ] = f2tf32f(scale[t    ]*(v0-mean)*inv + shift[t    ]);
    orow[t+256] = f2tf32f(scale[t+256]*(v1-mean)*inv + shift[t+256]);
    orow[t+512] = f2tf32f(scale[t+512]*(v2-mean)*inv + shift[t+512]);
    orow[t+768] = f2tf32f(scale[t+768]*(v3-mean)*inv + shift[t+768]);
}

// ======================= tf32 mma GEMM, cp.async double-buffered ============
// C[M,N] = A[M,K] @ W[K,N]; A,W pre-rounded to tf32 bit patterns.
// 256 threads = 8 warps (4m x 2n), block 128x128, warp tile 32x64, BK=32.
// EPI: 0 plain, 1 bias+residual, 2 gelu(bias).  RND: round output to tf32.
__device__ __forceinline__ float gelu_f(float x) {
    float u = 0.7978845608028654f * (x + 0.044715f * x * x * x);
    return 0.5f * x * (1.0f + tanhf(u));
}

#define AS_STRIDE 36
#define BS_STRIDE 136
#define SMEM_A_BYTES (128*AS_STRIDE*4)            // 18432
#define SMEM_B_BYTES (32*BS_STRIDE*4)             // 17408
#define SMEM_BUF     (SMEM_A_BYTES+SMEM_B_BYTES)  // 35840
#define GEMM_SMEM    (2*SMEM_BUF)                 // 71680

template<int EPI, int RND>
__global__ __launch_bounds__(256, 2)
void tgemm(const float* __restrict__ A, const float* __restrict__ W,
           const float* __restrict__ bias, const float* __restrict__ res,
           float* __restrict__ C, int N, int K)
{
    extern __shared__ char smem[];
    const uint32_t sb = smem_u32(smem);
    const int tid  = threadIdx.x;
    const int wid  = tid >> 5, lane = tid & 31;
    const int g    = lane >> 2, tg = lane & 3;
    const int wm   = (wid >> 1) * 32, wn = (wid & 1) * 64;
    const int brow = blockIdx.y * 128, bcol = blockIdx.x * 128;

    float acc[2][8][4];
    #pragma unroll
    for (int mi=0;mi<2;mi++)
        #pragma unroll
        for (int ni=0;ni<8;ni++)
            #pragma unroll
            for (int e=0;e<4;e++) acc[mi][ni][e]=0.f;

    auto stage = [&](int c, int buf) {
        uint32_t base = sb + buf * SMEM_BUF;
        int k0 = c * 32;
        #pragma unroll
        for (int it = 0; it < 4; it++) {               // A: 128x32
            int idx = it * 256 + tid;
            int row = idx >> 3, cc = (idx & 7) * 4;
            cp_async16(base + (uint32_t)(row * AS_STRIDE + cc) * 4,
                       A + (size_t)(brow + row) * K + k0 + cc);
        }
        #pragma unroll
        for (int it = 0; it < 4; it++) {               // B: 32x128
            int idx = it * 256 + tid;
            int row = idx >> 5, cc = (idx & 31) * 4;
            cp_async16(base + SMEM_A_BYTES + (uint32_t)(row * BS_STRIDE + cc) * 4,
                       W + (size_t)(k0 + row) * N + bcol + cc);
        }
        CP_COMMIT();
    };

    const int nch = K / 32;
    stage(0, 0);
    for (int c = 0; c < nch; c++) {
        if (c + 1 < nch) { stage(c + 1, (c + 1) & 1); CP_WAIT(1); }
        else             { CP_WAIT(0); }
        __syncthreads();
        const float* As = (const float*)(smem + (c & 1) * SMEM_BUF);
        const float* Bs = (const float*)(smem + (c & 1) * SMEM_BUF + SMEM_A_BYTES);

        #pragma unroll
        for (int kk = 0; kk < 32; kk += 8) {
            uint32_t af[2][4];
            #pragma unroll
            for (int mi = 0; mi < 2; mi++) {
                int r0 = wm + mi * 16 + g;
                af[mi][0] = __float_as_uint(As[r0       * AS_STRIDE + kk + tg    ]);
                af[mi][1] = __float_as_uint(As[(r0 + 8) * AS_STRIDE + kk + tg    ]);
                af[mi][2] = __float_as_uint(As[r0       * AS_STRIDE + kk + tg + 4]);
                af[mi][3] = __float_as_uint(As[(r0 + 8) * AS_STRIDE + kk + tg + 4]);
            }
            uint32_t bf[8][2];
            #pragma unroll
            for (int ni = 0; ni < 8; ni++) {
                int cI = wn + ni * 8 + g;
                bf[ni][0] = __float_as_uint(Bs[(kk + tg    ) * BS_STRIDE + cI]);
                bf[ni][1] = __float_as_uint(Bs[(kk + tg + 4) * BS_STRIDE + cI]);
            }
            #pragma unroll
            for (int mi = 0; mi < 2; mi++)
                #pragma unroll
                for (int ni = 0; ni < 8; ni++)
                    MMA_TF32(acc[mi][ni], af[mi][0], af[mi][1], af[mi][2], af[mi][3],
                             bf[ni][0], bf[ni][1]);
        }
        __syncthreads();
    }

    #pragma unroll
    for (int mi = 0; mi < 2; mi++) {
        int r0 = brow + wm + mi * 16 + g;
        #pragma unroll
        for (int ni = 0; ni < 8; ni++) {
            int c = bcol + wn + ni * 8 + 2 * tg;
            float v0 = acc[mi][ni][0], v1 = acc[mi][ni][1];
            float v2 = acc[mi][ni][2], v3 = acc[mi][ni][3];
            if (EPI == 1) {
                float b0 = bias[c], b1 = bias[c+1];
                const float* R0 = res + (size_t)r0 * N + c;
                const float* R1 = res + (size_t)(r0+8) * N + c;
                v0 += b0 + R0[0]; v1 += b1 + R0[1];
                v2 += b0 + R1[0]; v3 += b1 + R1[1];
            }
            if (EPI == 2) {
                float b0 = bias[c], b1 = bias[c+1];
                v0 = gelu_f(v0 + b0); v1 = gelu_f(v1 + b1);
                v2 = gelu_f(v2 + b0); v3 = gelu_f(v3 + b1);
            }
            if (RND) { v0=f2tf32f(v0); v1=f2tf32f(v1); v2=f2tf32f(v2); v3=f2tf32f(v3); }
            *(float2*)(C + (size_t)r0 * N + c)     = make_float2(v0, v1);
            *(float2*)(C + (size_t)(r0+8) * N + c) = make_float2(v2, v3);
        }
    }
}

// ======================= tensor-core causal flash attention =================
// block = 128 thr (4 warps), Q tile 64 rows, K/V tiles 64 keys.
// Inputs q,k,v pre-rounded tf32. Output ctx rounded tf32.
#define QS_STRIDE 68
#define KS_STRIDE 68
#define VS_STRIDE 72
#define PS_STRIDE 68
#define ATT_Q_OFF 0
#define ATT_K_OFF (64*QS_STRIDE)
#define ATT_V_OFF (ATT_K_OFF + 64*KS_STRIDE)
#define ATT_P_OFF (ATT_V_OFF + 64*VS_STRIDE)
#define ATT_SMEM  ((ATT_P_OFF + 64*PS_STRIDE)*4)   // 70656 bytes

__global__ __launch_bounds__(128)
void attn_kernel(const float* __restrict__ Q, const float* __restrict__ K,
                 const float* __restrict__ V, float* __restrict__ O)
{
    extern __shared__ float sm[];
    float* Qs = sm + ATT_Q_OFF;
    float* Ks = sm + ATT_K_OFF;
    float* Vs = sm + ATT_V_OFF;
    float* Ps = sm + ATT_P_OFF;

    const int qt = blockIdx.x, bh = blockIdx.y;
    const int b = bh >> 4, h = bh & 15;
    const int tid = threadIdx.x, w = tid >> 5, lane = tid & 31;
    const int g = lane >> 2, tg = lane & 3;
    const int r0 = 16 * w + g;

    // load Q tile (already tf32)
    #pragma unroll
    for (int it = 0; it < 8; it++) {
        int idx = it * 128 + tid;
        int row = idx >> 4, c4 = (idx & 15) * 4;
        *(float4*)(Qs + row * QS_STRIDE + c4) =
            *(const float4*)(Q + ((size_t)(b*SS + qt*64 + row))*DD + h*64 + c4);
    }

    float oacc[8][4];
    #pragma unroll
    for (int ni=0;ni<8;ni++)
        #pragma unroll
        for (int e=0;e<4;e++) oacc[ni][e]=0.f;
    float m0 = -INFINITY, m1 = -INFINITY, l0 = 0.f, l1 = 0.f;

    for (int kt = 0; kt <= qt; kt++) {
        __syncthreads();
        #pragma unroll
        for (int it = 0; it < 8; it++) {
            int idx = it * 128 + tid;
            int row = idx >> 4, c4 = (idx & 15) * 4;
            size_t goff = ((size_t)(b*SS + kt*64 + row))*DD + h*64 + c4;
            *(float4*)(Ks + row * KS_STRIDE + c4) = *(const float4*)(K + goff);
            *(float4*)(Vs + row * VS_STRIDE + c4) = *(const float4*)(V + goff);
        }
        __syncthreads();

        // S = Q K^T  (m16 rows per warp x 64 keys)
        float sacc[8][4];
        #pragma unroll
        for (int ni=0;ni<8;ni++)
            #pragma unroll
            for (int e=0;e<4;e++) sacc[ni][e]=0.f;

        #pragma unroll
        for (int kk = 0; kk < 64; kk += 8) {
            uint32_t a0 = __float_as_uint(Qs[r0      * QS_STRIDE + kk + tg    ]);
            uint32_t a1 = __float_as_uint(Qs[(r0+8)  * QS_STRIDE + kk + tg    ]);
            uint32_t a2 = __float_as_uint(Qs[r0      * QS_STRIDE + kk + tg + 4]);
            uint32_t a3 = __float_as_uint(Qs[(r0+8)  * QS_STRIDE + kk + tg + 4]);
            #pragma unroll
            for (int ni = 0; ni < 8; ni++) {
                int kr = ni * 8 + g;
                uint32_t b0 = __float_as_uint(Ks[kr * KS_STRIDE + kk + tg    ]);
                uint32_t b1 = __float_as_uint(Ks[kr * KS_STRIDE + kk + tg + 4]);
                MMA_TF32(sacc[ni], a0, a1, a2, a3, b0, b1);
            }
        }

        // scale + causal mask (diagonal tile only)
        const bool diag = (kt == qt);
        #pragma unroll
        for (int ni = 0; ni < 8; ni++) {
            #pragma unroll
            for (int e = 0; e < 4; e++) {
                float s = sacc[ni][e] * 0.125f;
                if (diag) {
                    int koff = ni * 8 + 2 * tg + (e & 1);
                    int qoff = 16 * w + g + ((e >= 2) ? 8 : 0);
                    if (koff > qoff) s = -INFINITY;
                }
                sacc[ni][e] = s;
            }
        }

        // online softmax (rows g and g+8; each row spread over 4 lanes)
        float rx0 = -INFINITY, rx1 = -INFINITY;
        #pragma unroll
        for (int ni = 0; ni < 8; ni++) {
            rx0 = fmaxf(rx0, fmaxf(sacc[ni][0], sacc[ni][1]));
            rx1 = fmaxf(rx1, fmaxf(sacc[ni][2], sacc[ni][3]));
        }
        rx0 = fmaxf(rx0, __shfl_xor_sync(0xffffffff, rx0, 1));
        rx0 = fmaxf(rx0, __shfl_xor_sync(0xffffffff, rx0, 2));
        rx1 = fmaxf(rx1, __shfl_xor_sync(0xffffffff, rx1, 1));
        rx1 = fmaxf(rx1, __shfl_xor_sync(0xffffffff, rx1, 2));
        float mn0 = fmaxf(m0, rx0), mn1 = fmaxf(m1, rx1);
        float c0 = __expf(m0 - mn0), c1 = __expf(m1 - mn1);

        float rs0 = 0.f, rs1 = 0.f;
        #pragma unroll
        for (int ni = 0; ni < 8; ni++) {
            float p0 = __expf(sacc[ni][0] - mn0);
            float p1 = __expf(sacc[ni][1] - mn0);
            float p2 = __expf(sacc[ni][2] - mn1);
            float p3 = __expf(sacc[ni][3] - mn1);
            rs0 += p0 + p1;  rs1 += p2 + p3;
            *(float2*)(Ps + r0     * PS_STRIDE + ni*8 + 2*tg) = make_float2(f2tf32f(p0), f2tf32f(p1));
            *(float2*)(Ps + (r0+8) * PS_STRIDE + ni*8 + 2*tg) = make_float2(f2tf32f(p2), f2tf32f(p3));
            oacc[ni][0] *= c0; oacc[ni][1] *= c0;
            oacc[ni][2] *= c1; oacc[ni][3] *= c1;
        }
        rs0 += __shfl_xor_sync(0xffffffff, rs0, 1);
        rs0 += __shfl_xor_sync(0xffffffff, rs0, 2);
        rs1 += __shfl_xor_sync(0xffffffff, rs1, 1);
        rs1 += __shfl_xor_sync(0xffffffff, rs1, 2);
        l0 = l0 * c0 + rs0;  l1 = l1 * c1 + rs1;
        m0 = mn0;  m1 = mn1;

        __syncwarp();

        // O += P V  (k = 64 keys)
        #pragma unroll
        for (int kk = 0; kk < 64; kk += 8) {
            uint32_t a0 = __float_as_uint(Ps[r0     * PS_STRIDE + kk + tg    ]);
            uint32_t a1 = __float_as_uint(Ps[(r0+8) * PS_STRIDE + kk + tg    ]);
            uint32_t a2 = __float_as_uint(Ps[r0     * PS_STRIDE + kk + tg + 4]);
            uint32_t a3 = __float_as_uint(Ps[(r0+8) * PS_STRIDE + kk + tg + 4]);
            #pragma unroll
            for (int ni = 0; ni < 8; ni++) {
                int dc = ni * 8 + g;
                uint32_t b0 = __float_as_uint(Vs[(kk + tg    ) * VS_STRIDE + dc]);
                uint32_t b1 = __float_as_uint(Vs[(kk + tg + 4) * VS_STRIDE + dc]);
                MMA_TF32(oacc[ni], a0, a1, a2, a3, b0, b1);
            }
        }
        __syncwarp();
    }

    float i0 = 1.f / l0, i1 = 1.f / l1;
    #pragma unroll
    for (int ni = 0; ni < 8; ni++) {
        int c = h * 64 + ni * 8 + 2 * tg;
        size_t go0 = ((size_t)(b*SS + qt*64 + 16*w + g)) * DD + c;
        *(float2*)(O + go0) = make_float2(f2tf32f(oacc[ni][0]*i0), f2tf32f(oacc[ni][1]*i0));
        *(float2*)(O + go0 + 8*DD) = make_float2(f2tf32f(oacc[ni][2]*i1), f2tf32f(oacc[ni][3]*i1));
    }
}

// ======================= launcher ===========================================
extern "C" void kernel_launch(void* const* d_in, const int* in_sizes, int n_in,
                              void* d_out, int out_size)
{
    const float* x    = (const float*)d_in[0];
    const float* Wq   = (const float*)d_in[1];
    const float* Wk   = (const float*)d_in[2];
    const float* Wv   = (const float*)d_in[3];
    const float* Wo   = (const float*)d_in[4];
    const float* bo   = (const float*)d_in[5];
    const float* W1   = (const float*)d_in[6];
    const float* b1   = (const float*)d_in[7];
    const float* W2   = (const float*)d_in[8];
    const float* b2   = (const float*)d_in[9];
    const float* ln1s = (const float*)d_in[10];
    const float* ln1b = (const float*)d_in[11];
    const float* ln2s = (const float*)d_in[12];
    const float* ln2b = (const float*)d_in[13];
    float* out = (float*)d_out;

    float *h,*q,*k,*v,*ctx,*x1,*ff,*wq,*wk,*wv,*wo,*w1,*w2;
    cudaGetSymbolAddress((void**)&h,   g_h);
    cudaGetSymbolAddress((void**)&q,   g_q);
    cudaGetSymbolAddress((void**)&k,   g_k);
    cudaGetSymbolAddress((void**)&v,   g_v);
    cudaGetSymbolAddress((void**)&ctx, g_ctx);
    cudaGetSymbolAddress((void**)&x1,  g_x1);
    cudaGetSymbolAddress((void**)&ff,  g_ff);
    cudaGetSymbolAddress((void**)&wq,  g_wq);
    cudaGetSymbolAddress((void**)&wk,  g_wk);
    cudaGetSymbolAddress((void**)&wv,  g_wv);
    cudaGetSymbolAddress((void**)&wo,  g_wo);
    cudaGetSymbolAddress((void**)&w1,  g_w1);
    cudaGetSymbolAddress((void**)&w2,  g_w2);

    cudaFuncSetAttribute(tgemm<0,1>, cudaFuncAttributeMaxDynamicSharedMemorySize, GEMM_SMEM);
    cudaFuncSetAttribute(tgemm<1,0>, cudaFuncAttributeMaxDynamicSharedMemorySize, GEMM_SMEM);
    cudaFuncSetAttribute(tgemm<2,1>, cudaFuncAttributeMaxDynamicSharedMemorySize, GEMM_SMEM);
    cudaFuncSetAttribute(attn_kernel, cudaFuncAttributeMaxDynamicSharedMemorySize, ATT_SMEM);

    // weights -> tf32 copies
    cvt_tf32_kernel<<<(DD*DD/4+255)/256,   256>>>(Wq, wq, DD*DD/4);
    cvt_tf32_kernel<<<(DD*DD/4+255)/256,   256>>>(Wk, wk, DD*DD/4);
    cvt_tf32_kernel<<<(DD*DD/4+255)/256,   256>>>(Wv, wv, DD*DD/4);
    cvt_tf32_kernel<<<(DD*DD/4+255)/256,   256>>>(Wo, wo, DD*DD/4);
    cvt_tf32_kernel<<<(DD*DFF/4+255)/256,  256>>>(W1, w1, DD*DFF/4);
    cvt_tf32_kernel<<<(DFF*DD/4+255)/256,  256>>>(W2, w2, DFF*DD/4);

    dim3 gD (DD/128,  ROWS/128);   // (8, 64)
    dim3 gFF(DFF/128, ROWS/128);   // (32, 64)

    ln_kernel<<<ROWS, 256>>>(x, ln1s, ln1b, h);
    tgemm<0,1><<<gD, 256, GEMM_SMEM>>>(h, wq, nullptr, nullptr, q, DD, DD);
    tgemm<0,1><<<gD, 256, GEMM_SMEM>>>(h, wk, nullptr, nullptr, k, DD, DD);
    tgemm<0,1><<<gD, 256, GEMM_SMEM>>>(h, wv, nullptr, nullptr, v, DD, DD);
    attn_kernel<<<dim3(SS/64, BB*HH), 128, ATT_SMEM>>>(q, k, v, ctx);
    tgemm<1,0><<<gD, 256, GEMM_SMEM>>>(ctx, wo, bo, x, x1, DD, DD);
    ln_kernel<<<ROWS, 256>>>(x1, ln2s, ln2b, h);
    tgemm<2,1><<<gFF, 256, GEMM_SMEM>>>(h, w1, b1, nullptr, ff, DFF, DD);
    tgemm<1,0><<<gD, 256, GEMM_SMEM>>>(ff, w2, b2, x1, out, DD, DFF);
}

// round 5
// speedup vs baseline: 4.7518x; 1.1868x over previous
#include <cuda_runtime.h>
#include <cuda_fp16.h>
#include <math.h>
#include <stdint.h>

#define BB   4
#define SS   2048
#define DD   1024
#define HH   16
#define HD   64
#define DFF  4096
#define ROWS (BB*SS)   // 8192

// ---------------- scratch (static device globals; no allocation) -----------
__device__ __half g_h  [ (size_t)ROWS*DD ];
__device__ __half g_q  [ (size_t)ROWS*DD ];
__device__ __half g_k  [ (size_t)ROWS*DD ];
__device__ __half g_v  [ (size_t)ROWS*DD ];
__device__ __half g_ctx[ (size_t)ROWS*DD ];
__device__ float  g_x1 [ (size_t)ROWS*DD ];
__device__ __half g_ff [ (size_t)ROWS*DFF ];
// fp16 weight copies (native [K,N] layout)
__device__ __half g_wq[ (size_t)DD*DD ];
__device__ __half g_wk[ (size_t)DD*DD ];
__device__ __half g_wv[ (size_t)DD*DD ];
__device__ __half g_wo[ (size_t)DD*DD ];
__device__ __half g_w1[ (size_t)DD*DFF ];
__device__ __half g_w2[ (size_t)DFF*DD ];

// ======================= helpers ============================================
__device__ __forceinline__ uint32_t smem_u32(const void* p) {
    uint32_t a;
    asm("{ .reg .u64 t; cvta.to.shared.u64 t, %1; cvt.u32.u64 %0, t; }" : "=r"(a) : "l"(p));
    return a;
}
__device__ __forceinline__ void cp_async16(uint32_t dst, const void* src) {
    asm volatile("cp.async.cg.shared.global [%0], [%1], 16;" :: "r"(dst), "l"(src));
}
#define CP_COMMIT() asm volatile("cp.async.commit_group;")
#define CP_WAIT(N)  asm volatile("cp.async.wait_group %0;" :: "n"(N))

#define LDSM_X4(r0,r1,r2,r3, addr) \
    asm volatile("ldmatrix.sync.aligned.m8n8.x4.shared.b16 {%0,%1,%2,%3}, [%4];" \
        : "=r"(r0),"=r"(r1),"=r"(r2),"=r"(r3) : "r"(addr))
#define LDSM_X4T(r0,r1,r2,r3, addr) \
    asm volatile("ldmatrix.sync.aligned.m8n8.x4.trans.shared.b16 {%0,%1,%2,%3}, [%4];" \
        : "=r"(r0),"=r"(r1),"=r"(r2),"=r"(r3) : "r"(addr))

#define MMA_F16(acc, a0,a1,a2,a3, b0,b1) \
    asm volatile("mma.sync.aligned.m16n8k16.row.col.f32.f16.f16.f32 " \
        "{%0,%1,%2,%3}, {%4,%5,%6,%7}, {%8,%9}, {%0,%1,%2,%3};" \
        : "+f"((acc)[0]), "+f"((acc)[1]), "+f"((acc)[2]), "+f"((acc)[3]) \
        : "r"(a0), "r"(a1), "r"(a2), "r"(a3), "r"(b0), "r"(b1))

// ======================= weight fp32 -> fp16 ================================
__global__ __launch_bounds__(256)
void cvt_half_kernel(const float* __restrict__ in, __half* __restrict__ out, int n2)
{
    int i = blockIdx.x * 256 + threadIdx.x;
    if (i < n2) {
        float2 v = ((const float2*)in)[i];
        ((__half2*)out)[i] = __floats2half2_rn(v.x, v.y);
    }
}

// ======================= LayerNorm (fp32 in, fp16 out) ======================
__global__ __launch_bounds__(256)
void ln_kernel(const float* __restrict__ x, const float* __restrict__ scale,
               const float* __restrict__ shift, __half* __restrict__ out)
{
    int row = blockIdx.x;
    const float* xr = x + (size_t)row * DD;
    __half* orow = out + (size_t)row * DD;
    int t = threadIdx.x;

    float v0 = xr[t], v1 = xr[t+256], v2 = xr[t+512], v3 = xr[t+768];
    float s  = v0+v1+v2+v3;
    float sq = v0*v0+v1*v1+v2*v2+v3*v3;

    __shared__ float red[2][256];
    red[0][t]=s; red[1][t]=sq; __syncthreads();
    for (int off=128; off>0; off>>=1) {
        if (t<off){ red[0][t]+=red[0][t+off]; red[1][t]+=red[1][t+off]; }
        __syncthreads();
    }
    float mean = red[0][0] * (1.0f/DD);
    float var  = red[1][0] * (1.0f/DD) - mean*mean;
    float inv  = rsqrtf(var + 1e-8f);

    orow[t    ] = __float2half_rn(scale[t    ]*(v0-mean)*inv + shift[t    ]);
    orow[t+256] = __float2half_rn(scale[t+256]*(v1-mean)*inv + shift[t+256]);
    orow[t+512] = __float2half_rn(scale[t+512]*(v2-mean)*inv + shift[t+512]);
    orow[t+768] = __float2half_rn(scale[t+768]*(v3-mean)*inv + shift[t+768]);
}

// ======================= fp16 mma GEMM, cp.async double-buffered ============
// C[M,N] = A[M,K] @ W[K,N]; A,W fp16, accumulate fp32.
// 256 threads = 8 warps (4m x 2n), block 128x128, warp tile 32x64, BK=32.
// EPI: 0 plain, 1 bias+residual(fp32), 2 gelu(bias). OUTH: fp16 output else fp32.
__device__ __forceinline__ float gelu_f(float x) {
    float u = 0.7978845608028654f * (x + 0.044715f * x * x * x);
    return 0.5f * x * (1.0f + tanhf(u));
}

#define AS_H 40          // A row stride (halves)
#define BS_H 136         // B row stride (halves)
#define SA_BYTES (128*AS_H*2)            // 10240
#define SB_BYTES (32*BS_H*2)             // 8704
#define STG_BYTES (SA_BYTES+SB_BYTES)    // 18944
#define GEMM_SMEM (2*STG_BYTES)          // 37888

template<int EPI, int OUTH>
__global__ __launch_bounds__(256, 2)
void tgemm(const __half* __restrict__ A, const __half* __restrict__ W,
           const float* __restrict__ bias, const float* __restrict__ res,
           void* __restrict__ C, int N, int K)
{
    extern __shared__ char smem[];
    const uint32_t sb = smem_u32(smem);
    const int tid  = threadIdx.x;
    const int wid  = tid >> 5, lane = tid & 31;
    const int g    = lane >> 2, tg = lane & 3;
    const int wm   = (wid >> 1) * 32, wn = (wid & 1) * 64;
    const int brow = blockIdx.y * 128, bcol = blockIdx.x * 128;

    float acc[2][8][4];
    #pragma unroll
    for (int mi=0;mi<2;mi++)
        #pragma unroll
        for (int ni=0;ni<8;ni++)
            #pragma unroll
            for (int e=0;e<4;e++) acc[mi][ni][e]=0.f;

    auto stage = [&](int c, int buf) {
        uint32_t base = sb + buf * STG_BYTES;
        int k0 = c * 32;
        #pragma unroll
        for (int it = 0; it < 2; it++) {               // A: 128x32 halves
            int idx = it * 256 + tid;
            int row = idx >> 2, c8 = (idx & 3) * 8;
            cp_async16(base + (uint32_t)(row * AS_H + c8) * 2,
                       A + (size_t)(brow + row) * K + k0 + c8);
        }
        #pragma unroll
        for (int it = 0; it < 2; it++) {               // B: 32x128 halves
            int idx = it * 256 + tid;
            int row = idx >> 4, c8 = (idx & 15) * 8;
            cp_async16(base + SA_BYTES + (uint32_t)(row * BS_H + c8) * 2,
                       W + (size_t)(k0 + row) * N + bcol + c8);
        }
        CP_COMMIT();
    };

    // precomputed intra-tile address components
    const uint32_t aoff = (uint32_t)((wm + (lane & 15)) * AS_H + 8 * (lane >> 4)) * 2;
    const uint32_t boff = (uint32_t)(((lane & 7) + 8 * ((lane >> 3) & 1)) * BS_H
                                     + wn + 8 * (lane >> 4)) * 2;

    const int nch = K / 32;
    stage(0, 0);
    for (int c = 0; c < nch; c++) {
        if (c + 1 < nch) { stage(c + 1, (c + 1) & 1); CP_WAIT(1); }
        else             { CP_WAIT(0); }
        __syncthreads();
        uint32_t sbuf = sb + (c & 1) * STG_BYTES;

        #pragma unroll
        for (int kb = 0; kb < 32; kb += 16) {
            uint32_t a[2][4];
            #pragma unroll
            for (int mi = 0; mi < 2; mi++)
                LDSM_X4(a[mi][0], a[mi][1], a[mi][2], a[mi][3],
                        sbuf + aoff + (uint32_t)(mi * 16 * AS_H + kb) * 2);
            #pragma unroll
            for (int np = 0; np < 4; np++) {
                uint32_t t0,t1,t2,t3;
                LDSM_X4T(t0,t1,t2,t3,
                         sbuf + SA_BYTES + boff + (uint32_t)(kb * BS_H + np * 16) * 2);
                #pragma unroll
                for (int mi = 0; mi < 2; mi++) {
                    MMA_F16(acc[mi][2*np],   a[mi][0],a[mi][1],a[mi][2],a[mi][3], t0,t1);
                    MMA_F16(acc[mi][2*np+1], a[mi][0],a[mi][1],a[mi][2],a[mi][3], t2,t3);
                }
            }
        }
        __syncthreads();
    }

    #pragma unroll
    for (int mi = 0; mi < 2; mi++) {
        int r0 = brow + wm + mi * 16 + g;
        #pragma unroll
        for (int ni = 0; ni < 8; ni++) {
            int c = bcol + wn + ni * 8 + 2 * tg;
            float v0 = acc[mi][ni][0], v1 = acc[mi][ni][1];
            float v2 = acc[mi][ni][2], v3 = acc[mi][ni][3];
            if (EPI == 1) {
                float b0 = bias[c], b1 = bias[c+1];
                const float* R0 = res + (size_t)r0 * N + c;
                const float* R1 = res + (size_t)(r0+8) * N + c;
                v0 += b0 + R0[0]; v1 += b1 + R0[1];
                v2 += b0 + R1[0]; v3 += b1 + R1[1];
            }
            if (EPI == 2) {
                float b0 = bias[c], b1 = bias[c+1];
                v0 = gelu_f(v0 + b0); v1 = gelu_f(v1 + b1);
                v2 = gelu_f(v2 + b0); v3 = gelu_f(v3 + b1);
            }
            if (OUTH) {
                __half* Ch = (__half*)C;
                *(__half2*)(Ch + (size_t)r0 * N + c)     = __floats2half2_rn(v0, v1);
                *(__half2*)(Ch + (size_t)(r0+8) * N + c) = __floats2half2_rn(v2, v3);
            } else {
                float* Cf = (float*)C;
                *(float2*)(Cf + (size_t)r0 * N + c)     = make_float2(v0, v1);
                *(float2*)(Cf + (size_t)(r0+8) * N + c) = make_float2(v2, v3);
            }
        }
    }
}

// ======================= fp16 tensor-core causal flash attention ============
// 256 thr (8 warps), Q tile 128 rows (warp w owns rows w*16..w*16+15),
// K/V tiles 64 keys, cp.async double-buffered.
#define AQ_H 72
#define ATT_Q_OFF 0                         // 128*72
#define ATT_K_OFF (128*AQ_H)                // 2 bufs x 64*72
#define ATT_V_OFF (ATT_K_OFF + 2*64*AQ_H)
#define ATT_P_OFF (ATT_V_OFF + 2*64*AQ_H)
#define ATT_SMEM  ((ATT_P_OFF + 128*AQ_H)*2)   // 73728 bytes

__global__ __launch_bounds__(256, 2)
void attn_kernel(const __half* __restrict__ Q, const __half* __restrict__ K,
                 const __half* __restrict__ V, __half* __restrict__ O)
{
    extern __shared__ __half sh[];
    const uint32_t sb = smem_u32(sh);

    const int qt = blockIdx.x, bh = blockIdx.y;
    const int b = bh >> 4, hh = bh & 15;
    const int tid = threadIdx.x, w = tid >> 5, lane = tid & 31;
    const int g = lane >> 2, tg = lane & 3;

    // load Q tile: 128 rows x 64 halves
    {
        const __half* Qg = Q + ((size_t)(b*SS + qt*128))*DD + hh*64;
        #pragma unroll
        for (int it = 0; it < 4; it++) {
            int idx = it * 256 + tid;
            int row = idx >> 3, c8 = (idx & 7) * 8;
            cp_async16(sb + (uint32_t)(ATT_Q_OFF + row * AQ_H + c8) * 2,
                       Qg + (size_t)row * DD + c8);
        }
    }
    auto loadKV = [&](int kt, int buf) {
        const __half* Kg = K + ((size_t)(b*SS + kt*64))*DD + hh*64;
        const __half* Vg = V + ((size_t)(b*SS + kt*64))*DD + hh*64;
        uint32_t kbase = sb + (uint32_t)(ATT_K_OFF + buf * 64 * AQ_H) * 2;
        uint32_t vbase = sb + (uint32_t)(ATT_V_OFF + buf * 64 * AQ_H) * 2;
        #pragma unroll
        for (int it = 0; it < 2; it++) {
            int idx = it * 256 + tid;
            int row = idx >> 3, c8 = (idx & 7) * 8;
            cp_async16(kbase + (uint32_t)(row * AQ_H + c8) * 2, Kg + (size_t)row * DD + c8);
            cp_async16(vbase + (uint32_t)(row * AQ_H + c8) * 2, Vg + (size_t)row * DD + c8);
        }
        CP_COMMIT();
    };

    float oacc[8][4];
    #pragma unroll
    for (int ni=0;ni<8;ni++)
        #pragma unroll
        for (int e=0;e<4;e++) oacc[ni][e]=0.f;
    float m0 = -INFINITY, m1 = -INFINITY, l0 = 0.f, l1 = 0.f;

    // address components
    const uint32_t qoff = (uint32_t)((w*16 + (lane & 15)) * AQ_H + 8 * (lane >> 4)) * 2;
    const uint32_t koff = (uint32_t)(((lane & 7) + 8 * (lane >> 4)) * AQ_H
                                     + 8 * ((lane >> 3) & 1)) * 2;   // K: non-trans B
    const uint32_t voff = (uint32_t)(((lane & 7) + 8 * ((lane >> 3) & 1)) * AQ_H
                                     + 8 * (lane >> 4)) * 2;          // V: trans B
    const uint32_t poff = qoff;  // P same layout as Q

    loadKV(0, 0);
    const int nkt = 2 * qt + 2;
    for (int kt = 0; kt < nkt; kt++) {
        int buf = kt & 1;
        if (kt + 1 < nkt) { loadKV(kt + 1, buf ^ 1); CP_WAIT(1); }
        else              { CP_WAIT(0); }
        __syncthreads();

        uint32_t kb_sm = sb + (uint32_t)(ATT_K_OFF + buf * 64 * AQ_H) * 2;
        uint32_t vb_sm = sb + (uint32_t)(ATT_V_OFF + buf * 64 * AQ_H) * 2;

        // S = Q K^T
        float sacc[8][4];
        #pragma unroll
        for (int ni=0;ni<8;ni++)
            #pragma unroll
            for (int e=0;e<4;e++) sacc[ni][e]=0.f;

        #pragma unroll
        for (int kb = 0; kb < 64; kb += 16) {
            uint32_t a0,a1,a2,a3;
            LDSM_X4(a0,a1,a2,a3, sb + (uint32_t)(ATT_Q_OFF)*2 + qoff + (uint32_t)kb * 2);
            #pragma unroll
            for (int np = 0; np < 4; np++) {
                uint32_t t0,t1,t2,t3;
                LDSM_X4(t0,t1,t2,t3, kb_sm + koff + (uint32_t)(np * 16 * AQ_H + kb) * 2);
                MMA_F16(sacc[2*np],   a0,a1,a2,a3, t0,t1);
                MMA_F16(sacc[2*np+1], a0,a1,a2,a3, t2,t3);
            }
        }

        // scale + causal mask
        const bool needMask = (kt * 64 + 63) > (qt * 128 + w * 16);
        const int qg0 = qt*128 + w*16 + g, qg1 = qg0 + 8;
        #pragma unroll
        for (int ni = 0; ni < 8; ni++) {
            int key0 = kt*64 + ni*8 + 2*tg;
            #pragma unroll
            for (int e = 0; e < 4; e++) {
                float s = sacc[ni][e] * 0.125f;
                if (needMask) {
                    int key = key0 + (e & 1);
                    int qr  = (e >= 2) ? qg1 : qg0;
                    if (key > qr) s = -INFINITY;
                }
                sacc[ni][e] = s;
            }
        }

        // online softmax
        float rx0 = -INFINITY, rx1 = -INFINITY;
        #pragma unroll
        for (int ni = 0; ni < 8; ni++) {
            rx0 = fmaxf(rx0, fmaxf(sacc[ni][0], sacc[ni][1]));
            rx1 = fmaxf(rx1, fmaxf(sacc[ni][2], sacc[ni][3]));
        }
        rx0 = fmaxf(rx0, __shfl_xor_sync(0xffffffff, rx0, 1));
        rx0 = fmaxf(rx0, __shfl_xor_sync(0xffffffff, rx0, 2));
        rx1 = fmaxf(rx1, __shfl_xor_sync(0xffffffff, rx1, 1));
        rx1 = fmaxf(rx1, __shfl_xor_sync(0xffffffff, rx1, 2));
        float mn0 = fmaxf(m0, rx0), mn1 = fmaxf(m1, rx1);
        float c0 = __expf(m0 - mn0), c1 = __expf(m1 - mn1);

        __half* Ps = sh + ATT_P_OFF;
        float rs0 = 0.f, rs1 = 0.f;
        #pragma unroll
        for (int ni = 0; ni < 8; ni++) {
            float p0 = __expf(sacc[ni][0] - mn0);
            float p1 = __expf(sacc[ni][1] - mn0);
            float p2 = __expf(sacc[ni][2] - mn1);
            float p3 = __expf(sacc[ni][3] - mn1);
            rs0 += p0 + p1;  rs1 += p2 + p3;
            *(__half2*)(Ps + (w*16 + g    ) * AQ_H + ni*8 + 2*tg) = __floats2half2_rn(p0, p1);
            *(__half2*)(Ps + (w*16 + g + 8) * AQ_H + ni*8 + 2*tg) = __floats2half2_rn(p2, p3);
            oacc[ni][0] *= c0; oacc[ni][1] *= c0;
            oacc[ni][2] *= c1; oacc[ni][3] *= c1;
        }
        rs0 += __shfl_xor_sync(0xffffffff, rs0, 1);
        rs0 += __shfl_xor_sync(0xffffffff, rs0, 2);
        rs1 += __shfl_xor_sync(0xffffffff, rs1, 1);
        rs1 += __shfl_xor_sync(0xffffffff, rs1, 2);
        l0 = l0 * c0 + rs0;  l1 = l1 * c1 + rs1;
        m0 = mn0;  m1 = mn1;

        __syncwarp();

        // O += P V
        #pragma unroll
        for (int kb = 0; kb < 64; kb += 16) {
            uint32_t a0,a1,a2,a3;
            LDSM_X4(a0,a1,a2,a3, sb + (uint32_t)(ATT_P_OFF)*2 + poff + (uint32_t)kb * 2);
            #pragma unroll
            for (int np = 0; np < 4; np++) {
                uint32_t t0,t1,t2,t3;
                LDSM_X4T(t0,t1,t2,t3, vb_sm + voff + (uint32_t)(kb * AQ_H + np * 16) * 2);
                MMA_F16(oacc[2*np],   a0,a1,a2,a3, t0,t1);
                MMA_F16(oacc[2*np+1], a0,a1,a2,a3, t2,t3);
            }
        }
        __syncthreads();
    }

    float i0 = 1.f / l0, i1 = 1.f / l1;
    #pragma unroll
    for (int ni = 0; ni < 8; ni++) {
        int c = hh*64 + ni*8 + 2*tg;
        size_t go = ((size_t)(b*SS + qt*128 + w*16 + g)) * DD + c;
        *(__half2*)(O + go)        = __floats2half2_rn(oacc[ni][0]*i0, oacc[ni][1]*i0);
        *(__half2*)(O + go + 8*DD) = __floats2half2_rn(oacc[ni][2]*i1, oacc[ni][3]*i1);
    }
}

// ======================= launcher ===========================================
extern "C" void kernel_launch(void* const* d_in, const int* in_sizes, int n_in,
                              void* d_out, int out_size)
{
    const float* x    = (const float*)d_in[0];
    const float* Wq   = (const float*)d_in[1];
    const float* Wk   = (const float*)d_in[2];
    const float* Wv   = (const float*)d_in[3];
    const float* Wo   = (const float*)d_in[4];
    const float* bo   = (const float*)d_in[5];
    const float* W1   = (const float*)d_in[6];
    const float* b1   = (const float*)d_in[7];
    const float* W2   = (const float*)d_in[8];
    const float* b2   = (const float*)d_in[9];
    const float* ln1s = (const float*)d_in[10];
    const float* ln1b = (const float*)d_in[11];
    const float* ln2s = (const float*)d_in[12];
    const float* ln2b = (const float*)d_in[13];
    float* out = (float*)d_out;

    __half *h,*q,*k,*v,*ctx,*ff,*wq,*wk,*wv,*wo,*w1,*w2;
    float *x1;
    cudaGetSymbolAddress((void**)&h,   g_h);
    cudaGetSymbolAddress((void**)&q,   g_q);
    cudaGetSymbolAddress((void**)&k,   g_k);
    cudaGetSymbolAddress((void**)&v,   g_v);
    cudaGetSymbolAddress((void**)&ctx, g_ctx);
    cudaGetSymbolAddress((void**)&x1,  g_x1);
    cudaGetSymbolAddress((void**)&ff,  g_ff);
    cudaGetSymbolAddress((void**)&wq,  g_wq);
    cudaGetSymbolAddress((void**)&wk,  g_wk);
    cudaGetSymbolAddress((void**)&wv,  g_wv);
    cudaGetSymbolAddress((void**)&wo,  g_wo);
    cudaGetSymbolAddress((void**)&w1,  g_w1);
    cudaGetSymbolAddress((void**)&w2,  g_w2);

    cudaFuncSetAttribute(tgemm<0,1>, cudaFuncAttributeMaxDynamicSharedMemorySize, GEMM_SMEM);
    cudaFuncSetAttribute(tgemm<1,0>, cudaFuncAttributeMaxDynamicSharedMemorySize, GEMM_SMEM);
    cudaFuncSetAttribute(tgemm<2,1>, cudaFuncAttributeMaxDynamicSharedMemorySize, GEMM_SMEM);
    cudaFuncSetAttribute(attn_kernel, cudaFuncAttributeMaxDynamicSharedMemorySize, ATT_SMEM);

    // weights -> fp16 copies
    cvt_half_kernel<<<(DD*DD/2+255)/256,  256>>>(Wq, wq, DD*DD/2);
    cvt_half_kernel<<<(DD*DD/2+255)/256,  256>>>(Wk, wk, DD*DD/2);
    cvt_half_kernel<<<(DD*DD/2+255)/256,  256>>>(Wv, wv, DD*DD/2);
    cvt_half_kernel<<<(DD*DD/2+255)/256,  256>>>(Wo, wo, DD*DD/2);
    cvt_half_kernel<<<(DD*DFF/2+255)/256, 256>>>(W1, w1, DD*DFF/2);
    cvt_half_kernel<<<(DFF*DD/2+255)/256, 256>>>(W2, w2, DFF*DD/2);

    dim3 gD (DD/128,  ROWS/128);   // (8, 64)
    dim3 gFF(DFF/128, ROWS/128);   // (32, 64)

    ln_kernel<<<ROWS, 256>>>(x, ln1s, ln1b, h);
    tgemm<0,1><<<gD, 256, GEMM_SMEM>>>(h, wq, nullptr, nullptr, q, DD, DD);
    tgemm<0,1><<<gD, 256, GEMM_SMEM>>>(h, wk, nullptr, nullptr, k, DD, DD);
    tgemm<0,1><<<gD, 256, GEMM_SMEM>>>(h, wv, nullptr, nullptr, v, DD, DD);
    attn_kernel<<<dim3(SS/128, BB*HH), 256, ATT_SMEM>>>(q, k, v, ctx);
    tgemm<1,0><<<gD, 256, GEMM_SMEM>>>(ctx, wo, bo, x, x1, DD, DD);
    ln_kernel<<<ROWS, 256>>>(x1, ln2s, ln2b, h);
    tgemm<2,1><<<gFF, 256, GEMM_SMEM>>>(h, w1, b1, nullptr, ff, DFF, DD);
    tgemm<1,0><<<gD, 256, GEMM_SMEM>>>(ff, w2, b2, x1, out, DD, DFF);
}

// round 6
// speedup vs baseline: 8.1488x; 1.7149x over previous
#include <cuda_runtime.h>
#include <cuda_fp16.h>
#include <math.h>
#include <stdint.h>

#define BB   4
#define SS   2048
#define DD   1024
#define HH   16
#define HD   64
#define DFF  4096
#define ROWS (BB*SS)   // 8192
#define QST  (3*DD)    // qkv row stride

// ---------------- scratch (static device globals; no allocation) -----------
__device__ __half g_h   [ (size_t)ROWS*DD ];
__device__ __half g_qkv [ (size_t)ROWS*QST ];
__device__ __half g_ctx [ (size_t)ROWS*DD ];
__device__ float  g_x1  [ (size_t)ROWS*DD ];
__device__ __half g_ff  [ (size_t)ROWS*DFF ];
// fp16 weights: wqkv = [Wq|Wk|Wv] concatenated along N
__device__ __half g_wqkv[ (size_t)DD*QST ];
__device__ __half g_wo  [ (size_t)DD*DD ];
__device__ __half g_w1  [ (size_t)DD*DFF ];
__device__ __half g_w2  [ (size_t)DFF*DD ];

// ======================= helpers ============================================
__device__ __forceinline__ uint32_t smem_u32(const void* p) {
    uint32_t a;
    asm("{ .reg .u64 t; cvta.to.shared.u64 t, %1; cvt.u32.u64 %0, t; }" : "=r"(a) : "l"(p));
    return a;
}
__device__ __forceinline__ void cp_async16(uint32_t dst, const void* src) {
    asm volatile("cp.async.cg.shared.global [%0], [%1], 16;" :: "r"(dst), "l"(src));
}
#define CP_COMMIT() asm volatile("cp.async.commit_group;")
#define CP_WAIT(N)  asm volatile("cp.async.wait_group %0;" :: "n"(N))

#define LDSM_X4(r0,r1,r2,r3, addr) \
    asm volatile("ldmatrix.sync.aligned.m8n8.x4.shared.b16 {%0,%1,%2,%3}, [%4];" \
        : "=r"(r0),"=r"(r1),"=r"(r2),"=r"(r3) : "r"(addr))
#define LDSM_X4T(r0,r1,r2,r3, addr) \
    asm volatile("ldmatrix.sync.aligned.m8n8.x4.trans.shared.b16 {%0,%1,%2,%3}, [%4];" \
        : "=r"(r0),"=r"(r1),"=r"(r2),"=r"(r3) : "r"(addr))

#define MMA_F16(acc, a0,a1,a2,a3, b0,b1) \
    asm volatile("mma.sync.aligned.m16n8k16.row.col.f32.f16.f16.f32 " \
        "{%0,%1,%2,%3}, {%4,%5,%6,%7}, {%8,%9}, {%0,%1,%2,%3};" \
        : "+f"((acc)[0]), "+f"((acc)[1]), "+f"((acc)[2]), "+f"((acc)[3]) \
        : "r"(a0), "r"(a1), "r"(a2), "r"(a3), "r"(b0), "r"(b1))

// ====== weight fp32 -> fp16 with strided (concat) destination ===============
__global__ __launch_bounds__(256)
void cvt_half_strided(const float* __restrict__ in, __half* __restrict__ out,
                      int ncols2, int ostride2, int total2)
{
    int i = blockIdx.x * 256 + threadIdx.x;
    if (i < total2) {
        int r = i / ncols2, c2 = i - r * ncols2;
        float2 v = ((const float2*)in)[i];
        ((__half2*)out)[(size_t)r * ostride2 + c2] = __floats2half2_rn(v.x, v.y);
    }
}

// ======================= LayerNorm (fp32 in, fp16 out) ======================
__global__ __launch_bounds__(256)
void ln_kernel(const float* __restrict__ x, const float* __restrict__ scale,
               const float* __restrict__ shift, __half* __restrict__ out)
{
    int row = blockIdx.x;
    const float* xr = x + (size_t)row * DD;
    __half* orow = out + (size_t)row * DD;
    int t = threadIdx.x;

    float v0 = xr[t], v1 = xr[t+256], v2 = xr[t+512], v3 = xr[t+768];
    float s  = v0+v1+v2+v3;
    float sq = v0*v0+v1*v1+v2*v2+v3*v3;

    __shared__ float red[2][256];
    red[0][t]=s; red[1][t]=sq; __syncthreads();
    for (int off=128; off>0; off>>=1) {
        if (t<off){ red[0][t]+=red[0][t+off]; red[1][t]+=red[1][t+off]; }
        __syncthreads();
    }
    float mean = red[0][0] * (1.0f/DD);
    float var  = red[1][0] * (1.0f/DD) - mean*mean;
    float inv  = rsqrtf(var + 1e-8f);

    orow[t    ] = __float2half_rn(scale[t    ]*(v0-mean)*inv + shift[t    ]);
    orow[t+256] = __float2half_rn(scale[t+256]*(v1-mean)*inv + shift[t+256]);
    orow[t+512] = __float2half_rn(scale[t+512]*(v2-mean)*inv + shift[t+512]);
    orow[t+768] = __float2half_rn(scale[t+768]*(v3-mean)*inv + shift[t+768]);
}

// ================= fp16 mma GEMM, 3-stage cp.async, warp tile 64x64 =========
// C[M,N] = A[M,K] @ W[K,N]; 128 thr = 4 warps (2m x 2n), block 128x128.
// EPI: 0 plain, 1 bias+residual(fp32), 2 gelu(bias). OUTH: fp16 out else fp32.
__device__ __forceinline__ float gelu_f(float x) {
    float u = 0.7978845608028654f * (x + 0.044715f * x * x * x);
    return 0.5f * x * (1.0f + tanhf(u));
}

#define AS_H 40
#define BS_H 136
#define SA_BYTES (128*AS_H*2)            // 10240
#define SB_BYTES (32*BS_H*2)             // 8704
#define STG_BYTES (SA_BYTES+SB_BYTES)    // 18944
#define GEMM_SMEM (3*STG_BYTES)          // 56832

template<int EPI, int OUTH>
__global__ __launch_bounds__(128, 2)
void tgemm(const __half* __restrict__ A, const __half* __restrict__ W,
           const float* __restrict__ bias, const float* __restrict__ res,
           void* __restrict__ C, int N, int K)
{
    extern __shared__ char smem[];
    const uint32_t sb = smem_u32(smem);
    const int tid  = threadIdx.x;
    const int wid  = tid >> 5, lane = tid & 31;
    const int g    = lane >> 2, tg = lane & 3;
    const int wm   = (wid >> 1) * 64, wn = (wid & 1) * 64;
    const int brow = blockIdx.y * 128, bcol = blockIdx.x * 128;

    float acc[4][8][4];
    #pragma unroll
    for (int mi=0;mi<4;mi++)
        #pragma unroll
        for (int ni=0;ni<8;ni++)
            #pragma unroll
            for (int e=0;e<4;e++) acc[mi][ni][e]=0.f;

    auto stage = [&](int c, int buf) {
        uint32_t base = sb + buf * STG_BYTES;
        int k0 = c * 32;
        #pragma unroll
        for (int it = 0; it < 4; it++) {               // A: 128x32 halves
            int idx = it * 128 + tid;
            int row = idx >> 2, c8 = (idx & 3) * 8;
            cp_async16(base + (uint32_t)(row * AS_H + c8) * 2,
                       A + (size_t)(brow + row) * K + k0 + c8);
        }
        #pragma unroll
        for (int it = 0; it < 4; it++) {               // B: 32x128 halves
            int idx = it * 128 + tid;
            int row = idx >> 4, c8 = (idx & 15) * 8;
            cp_async16(base + SA_BYTES + (uint32_t)(row * BS_H + c8) * 2,
                       W + (size_t)(k0 + row) * N + bcol + c8);
        }
        CP_COMMIT();
    };

    const uint32_t aoff = (uint32_t)((wm + (lane & 15)) * AS_H + 8 * (lane >> 4)) * 2;
    const uint32_t boff = (uint32_t)(((lane & 7) + 8 * ((lane >> 3) & 1)) * BS_H
                                     + wn + 8 * (lane >> 4)) * 2;

    const int nch = K / 32;
    stage(0, 0);
    stage(1, 1);
    for (int c = 0; c < nch; c++) {
        if (c + 2 < nch)      { stage(c + 2, (c + 2) % 3); CP_WAIT(2); }
        else if (c + 1 < nch) { CP_WAIT(1); }
        else                  { CP_WAIT(0); }
        __syncthreads();
        uint32_t sbuf = sb + (c % 3) * STG_BYTES;

        #pragma unroll
        for (int kb = 0; kb < 32; kb += 16) {
            uint32_t a[4][4];
            #pragma unroll
            for (int mi = 0; mi < 4; mi++)
                LDSM_X4(a[mi][0], a[mi][1], a[mi][2], a[mi][3],
                        sbuf + aoff + (uint32_t)(mi * 16 * AS_H + kb) * 2);
            #pragma unroll
            for (int np = 0; np < 4; np++) {
                uint32_t t0,t1,t2,t3;
                LDSM_X4T(t0,t1,t2,t3,
                         sbuf + SA_BYTES + boff + (uint32_t)(kb * BS_H + np * 16) * 2);
                #pragma unroll
                for (int mi = 0; mi < 4; mi++) {
                    MMA_F16(acc[mi][2*np],   a[mi][0],a[mi][1],a[mi][2],a[mi][3], t0,t1);
                    MMA_F16(acc[mi][2*np+1], a[mi][0],a[mi][1],a[mi][2],a[mi][3], t2,t3);
                }
            }
        }
        __syncthreads();
    }

    #pragma unroll
    for (int mi = 0; mi < 4; mi++) {
        int r0 = brow + wm + mi * 16 + g;
        #pragma unroll
        for (int ni = 0; ni < 8; ni++) {
            int c = bcol + wn + ni * 8 + 2 * tg;
            float v0 = acc[mi][ni][0], v1 = acc[mi][ni][1];
            float v2 = acc[mi][ni][2], v3 = acc[mi][ni][3];
            if (EPI == 1) {
                float b0 = bias[c], b1 = bias[c+1];
                const float* R0 = res + (size_t)r0 * N + c;
                const float* R1 = res + (size_t)(r0+8) * N + c;
                v0 += b0 + R0[0]; v1 += b1 + R0[1];
                v2 += b0 + R1[0]; v3 += b1 + R1[1];
            }
            if (EPI == 2) {
                float b0 = bias[c], b1 = bias[c+1];
                v0 = gelu_f(v0 + b0); v1 = gelu_f(v1 + b1);
                v2 = gelu_f(v2 + b0); v3 = gelu_f(v3 + b1);
            }
            if (OUTH) {
                __half* Ch = (__half*)C;
                *(__half2*)(Ch + (size_t)r0 * N + c)     = __floats2half2_rn(v0, v1);
                *(__half2*)(Ch + (size_t)(r0+8) * N + c) = __floats2half2_rn(v2, v3);
            } else {
                float* Cf = (float*)C;
                *(float2*)(Cf + (size_t)r0 * N + c)     = make_float2(v0, v1);
                *(float2*)(Cf + (size_t)(r0+8) * N + c) = make_float2(v2, v3);
            }
        }
    }
}

// ======================= fp16 tensor-core causal flash attention ============
// 256 thr (8 warps), Q tile 128 rows, K/V tiles 64 keys, cp.async 2-stage.
// q,k,v read from packed qkv [ROWS, 3*DD].
#define AQ_H 72
#define ATT_Q_OFF 0
#define ATT_K_OFF (128*AQ_H)
#define ATT_V_OFF (ATT_K_OFF + 2*64*AQ_H)
#define ATT_P_OFF (ATT_V_OFF + 2*64*AQ_H)
#define ATT_SMEM  ((ATT_P_OFF + 128*AQ_H)*2)   // 73728 bytes

__global__ __launch_bounds__(256, 2)
void attn_kernel(const __half* __restrict__ QKV, __half* __restrict__ O)
{
    extern __shared__ __half sh[];
    const uint32_t sb = smem_u32(sh);

    const int qt = blockIdx.x, bh = blockIdx.y;
    const int b = bh >> 4, hh = bh & 15;
    const int tid = threadIdx.x, w = tid >> 5, lane = tid & 31;
    const int g = lane >> 2, tg = lane & 3;

    {
        const __half* Qg = QKV + ((size_t)(b*SS + qt*128))*QST + hh*64;
        #pragma unroll
        for (int it = 0; it < 4; it++) {
            int idx = it * 256 + tid;
            int row = idx >> 3, c8 = (idx & 7) * 8;
            cp_async16(sb + (uint32_t)(ATT_Q_OFF + row * AQ_H + c8) * 2,
                       Qg + (size_t)row * QST + c8);
        }
    }
    auto loadKV = [&](int kt, int buf) {
        const __half* Kg = QKV + ((size_t)(b*SS + kt*64))*QST + DD   + hh*64;
        const __half* Vg = QKV + ((size_t)(b*SS + kt*64))*QST + 2*DD + hh*64;
        uint32_t kbase = sb + (uint32_t)(ATT_K_OFF + buf * 64 * AQ_H) * 2;
        uint32_t vbase = sb + (uint32_t)(ATT_V_OFF + buf * 64 * AQ_H) * 2;
        #pragma unroll
        for (int it = 0; it < 2; it++) {
            int idx = it * 256 + tid;
            int row = idx >> 3, c8 = (idx & 7) * 8;
            cp_async16(kbase + (uint32_t)(row * AQ_H + c8) * 2, Kg + (size_t)row * QST + c8);
            cp_async16(vbase + (uint32_t)(row * AQ_H + c8) * 2, Vg + (size_t)row * QST + c8);
        }
        CP_COMMIT();
    };

    float oacc[8][4];
    #pragma unroll
    for (int ni=0;ni<8;ni++)
        #pragma unroll
        for (int e=0;e<4;e++) oacc[ni][e]=0.f;
    float m0 = -INFINITY, m1 = -INFINITY, l0 = 0.f, l1 = 0.f;

    const uint32_t qoff = (uint32_t)((w*16 + (lane & 15)) * AQ_H + 8 * (lane >> 4)) * 2;
    const uint32_t koff = (uint32_t)(((lane & 7) + 8 * (lane >> 4)) * AQ_H
                                     + 8 * ((lane >> 3) & 1)) * 2;
    const uint32_t voff = (uint32_t)(((lane & 7) + 8 * ((lane >> 3) & 1)) * AQ_H
                                     + 8 * (lane >> 4)) * 2;
    const uint32_t poff = qoff;

    loadKV(0, 0);
    const int nkt = 2 * qt + 2;
    for (int kt = 0; kt < nkt; kt++) {
        int buf = kt & 1;
        if (kt + 1 < nkt) { loadKV(kt + 1, buf ^ 1); CP_WAIT(1); }
        else              { CP_WAIT(0); }
        __syncthreads();

        uint32_t kb_sm = sb + (uint32_t)(ATT_K_OFF + buf * 64 * AQ_H) * 2;
        uint32_t vb_sm = sb + (uint32_t)(ATT_V_OFF + buf * 64 * AQ_H) * 2;

        float sacc[8][4];
        #pragma unroll
        for (int ni=0;ni<8;ni++)
            #pragma unroll
            for (int e=0;e<4;e++) sacc[ni][e]=0.f;

        #pragma unroll
        for (int kb = 0; kb < 64; kb += 16) {
            uint32_t a0,a1,a2,a3;
            LDSM_X4(a0,a1,a2,a3, sb + (uint32_t)(ATT_Q_OFF)*2 + qoff + (uint32_t)kb * 2);
            #pragma unroll
            for (int np = 0; np < 4; np++) {
                uint32_t t0,t1,t2,t3;
                LDSM_X4(t0,t1,t2,t3, kb_sm + koff + (uint32_t)(np * 16 * AQ_H + kb) * 2);
                MMA_F16(sacc[2*np],   a0,a1,a2,a3, t0,t1);
                MMA_F16(sacc[2*np+1], a0,a1,a2,a3, t2,t3);
            }
        }

        const bool needMask = (kt * 64 + 63) > (qt * 128 + w * 16);
        const int qg0 = qt*128 + w*16 + g, qg1 = qg0 + 8;
        #pragma unroll
        for (int ni = 0; ni < 8; ni++) {
            int key0 = kt*64 + ni*8 + 2*tg;
            #pragma unroll
            for (int e = 0; e < 4; e++) {
                float s = sacc[ni][e] * 0.125f;
                if (needMask) {
                    int key = key0 + (e & 1);
                    int qr  = (e >= 2) ? qg1 : qg0;
                    if (key > qr) s = -INFINITY;
                }
                sacc[ni][e] = s;
            }
        }

        float rx0 = -INFINITY, rx1 = -INFINITY;
        #pragma unroll
        for (int ni = 0; ni < 8; ni++) {
            rx0 = fmaxf(rx0, fmaxf(sacc[ni][0], sacc[ni][1]));
            rx1 = fmaxf(rx1, fmaxf(sacc[ni][2], sacc[ni][3]));
        }
        rx0 = fmaxf(rx0, __shfl_xor_sync(0xffffffff, rx0, 1));
        rx0 = fmaxf(rx0, __shfl_xor_sync(0xffffffff, rx0, 2));
        rx1 = fmaxf(rx1, __shfl_xor_sync(0xffffffff, rx1, 1));
        rx1 = fmaxf(rx1, __shfl_xor_sync(0xffffffff, rx1, 2));
        float mn0 = fmaxf(m0, rx0), mn1 = fmaxf(m1, rx1);
        float c0 = __expf(m0 - mn0), c1 = __expf(m1 - mn1);

        __half* Ps = sh + ATT_P_OFF;
        float rs0 = 0.f, rs1 = 0.f;
        #pragma unroll
        for (int ni = 0; ni < 8; ni++) {
            float p0 = __expf(sacc[ni][0] - mn0);
            float p1 = __expf(sacc[ni][1] - mn0);
            float p2 = __expf(sacc[ni][2] - mn1);
            float p3 = __expf(sacc[ni][3] - mn1);
            rs0 += p0 + p1;  rs1 += p2 + p3;
            *(__half2*)(Ps + (w*16 + g    ) * AQ_H + ni*8 + 2*tg) = __floats2half2_rn(p0, p1);
            *(__half2*)(Ps + (w*16 + g + 8) * AQ_H + ni*8 + 2*tg) = __floats2half2_rn(p2, p3);
            oacc[ni][0] *= c0; oacc[ni][1] *= c0;
            oacc[ni][2] *= c1; oacc[ni][3] *= c1;
        }
        rs0 += __shfl_xor_sync(0xffffffff, rs0, 1);
        rs0 += __shfl_xor_sync(0xffffffff, rs0, 2);
        rs1 += __shfl_xor_sync(0xffffffff, rs1, 1);
        rs1 += __shfl_xor_sync(0xffffffff, rs1, 2);
        l0 = l0 * c0 + rs0;  l1 = l1 * c1 + rs1;
        m0 = mn0;  m1 = mn1;

        __syncwarp();

        #pragma unroll
        for (int kb = 0; kb < 64; kb += 16) {
            uint32_t a0,a1,a2,a3;
            LDSM_X4(a0,a1,a2,a3, sb + (uint32_t)(ATT_P_OFF)*2 + poff + (uint32_t)kb * 2);
            #pragma unroll
            for (int np = 0; np < 4; np++) {
                uint32_t t0,t1,t2,t3;
                LDSM_X4T(t0,t1,t2,t3, vb_sm + voff + (uint32_t)(kb * AQ_H + np * 16) * 2);
                MMA_F16(oacc[2*np],   a0,a1,a2,a3, t0,t1);
                MMA_F16(oacc[2*np+1], a0,a1,a2,a3, t2,t3);
            }
        }
        __syncthreads();
    }

    float i0 = 1.f / l0, i1 = 1.f / l1;
    #pragma unroll
    for (int ni = 0; ni < 8; ni++) {
        int c = hh*64 + ni*8 + 2*tg;
        size_t go = ((size_t)(b*SS + qt*128 + w*16 + g)) * DD + c;
        *(__half2*)(O + go)        = __floats2half2_rn(oacc[ni][0]*i0, oacc[ni][1]*i0);
        *(__half2*)(O + go + 8*DD) = __floats2half2_rn(oacc[ni][2]*i1, oacc[ni][3]*i1);
    }
}

// ======================= launcher ===========================================
extern "C" void kernel_launch(void* const* d_in, const int* in_sizes, int n_in,
                              void* d_out, int out_size)
{
    const float* x    = (const float*)d_in[0];
    const float* Wq   = (const float*)d_in[1];
    const float* Wk   = (const float*)d_in[2];
    const float* Wv   = (const float*)d_in[3];
    const float* Wo   = (const float*)d_in[4];
    const float* bo   = (const float*)d_in[5];
    const float* W1   = (const float*)d_in[6];
    const float* b1   = (const float*)d_in[7];
    const float* W2   = (const float*)d_in[8];
    const float* b2   = (const float*)d_in[9];
    const float* ln1s = (const float*)d_in[10];
    const float* ln1b = (const float*)d_in[11];
    const float* ln2s = (const float*)d_in[12];
    const float* ln2b = (const float*)d_in[13];
    float* out = (float*)d_out;

    __half *h,*qkv,*ctx,*ff,*wqkv,*wo,*w1,*w2;
    float *x1;
    cudaGetSymbolAddress((void**)&h,    g_h);
    cudaGetSymbolAddress((void**)&qkv,  g_qkv);
    cudaGetSymbolAddress((void**)&ctx,  g_ctx);
    cudaGetSymbolAddress((void**)&x1,   g_x1);
    cudaGetSymbolAddress((void**)&ff,   g_ff);
    cudaGetSymbolAddress((void**)&wqkv, g_wqkv);
    cudaGetSymbolAddress((void**)&wo,   g_wo);
    cudaGetSymbolAddress((void**)&w1,   g_w1);
    cudaGetSymbolAddress((void**)&w2,   g_w2);

    cudaFuncSetAttribute(tgemm<0,1>, cudaFuncAttributeMaxDynamicSharedMemorySize, GEMM_SMEM);
    cudaFuncSetAttribute(tgemm<1,0>, cudaFuncAttributeMaxDynamicSharedMemorySize, GEMM_SMEM);
    cudaFuncSetAttribute(tgemm<2,1>, cudaFuncAttributeMaxDynamicSharedMemorySize, GEMM_SMEM);
    cudaFuncSetAttribute(attn_kernel, cudaFuncAttributeMaxDynamicSharedMemorySize, ATT_SMEM);

    const int n2D = DD*DD/2;
    cvt_half_strided<<<(n2D+255)/256, 256>>>(Wq, wqkv,          DD/2, QST/2, n2D);
    cvt_half_strided<<<(n2D+255)/256, 256>>>(Wk, wqkv + DD,     DD/2, QST/2, n2D);
    cvt_half_strided<<<(n2D+255)/256, 256>>>(Wv, wqkv + 2*DD,   DD/2, QST/2, n2D);
    cvt_half_strided<<<(n2D+255)/256, 256>>>(Wo, wo,            DD/2, DD/2,  n2D);
    cvt_half_strided<<<(DD*DFF/2+255)/256, 256>>>(W1, w1, DFF/2, DFF/2, DD*DFF/2);
    cvt_half_strided<<<(DFF*DD/2+255)/256, 256>>>(W2, w2, DD/2,  DD/2,  DFF*DD/2);

    dim3 gQKV(QST/128, ROWS/128);  // (24, 64)
    dim3 gD  (DD/128,  ROWS/128);  // (8, 64)
    dim3 gFF (DFF/128, ROWS/128);  // (32, 64)

    ln_kernel<<<ROWS, 256>>>(x, ln1s, ln1b, h);
    tgemm<0,1><<<gQKV, 128, GEMM_SMEM>>>(h, wqkv, nullptr, nullptr, qkv, QST, DD);
    attn_kernel<<<dim3(SS/128, BB*HH), 256, ATT_SMEM>>>(qkv, ctx);
    tgemm<1,0><<<gD, 128, GEMM_SMEM>>>(ctx, wo, bo, x, x1, DD, DD);
    ln_kernel<<<ROWS, 256>>>(x1, ln2s, ln2b, h);
    tgemm<2,1><<<gFF, 128, GEMM_SMEM>>>(h, w1, b1, nullptr, ff, DFF, DD);
    tgemm<1,0><<<gD, 128, GEMM_SMEM>>>(ff, w2, b2, x1, out, DD, DFF);
}

// round 7
// speedup vs baseline: 8.4961x; 1.0426x over previous
#include <cuda_runtime.h>
#include <cuda_fp16.h>
#include <math.h>
#include <stdint.h>

#define BB   4
#define SS   2048
#define DD   1024
#define HH   16
#define HD   64
#define DFF  4096
#define ROWS (BB*SS)   // 8192
#define QST  (3*DD)    // qkv row stride

// ---------------- scratch (static device globals; no allocation) -----------
__device__ __half g_h   [ (size_t)ROWS*DD ];
__device__ __half g_qkv [ (size_t)ROWS*QST ];
__device__ __half g_ctx [ (size_t)ROWS*DD ];
__device__ float  g_x1  [ (size_t)ROWS*DD ];
__device__ __half g_ff  [ (size_t)ROWS*DFF ];
__device__ __half g_wqkv[ (size_t)DD*QST ];
__device__ __half g_wo  [ (size_t)DD*DD ];
__device__ __half g_w1  [ (size_t)DD*DFF ];
__device__ __half g_w2  [ (size_t)DFF*DD ];

// ======================= helpers ============================================
__device__ __forceinline__ uint32_t smem_u32(const void* p) {
    uint32_t a;
    asm("{ .reg .u64 t; cvta.to.shared.u64 t, %1; cvt.u32.u64 %0, t; }" : "=r"(a) : "l"(p));
    return a;
}
__device__ __forceinline__ void cp_async16(uint32_t dst, const void* src) {
    asm volatile("cp.async.cg.shared.global [%0], [%1], 16;" :: "r"(dst), "l"(src));
}
#define CP_COMMIT() asm volatile("cp.async.commit_group;")
#define CP_WAIT(N)  asm volatile("cp.async.wait_group %0;" :: "n"(N))

#define LDSM_X4(r0,r1,r2,r3, addr) \
    asm volatile("ldmatrix.sync.aligned.m8n8.x4.shared.b16 {%0,%1,%2,%3}, [%4];" \
        : "=r"(r0),"=r"(r1),"=r"(r2),"=r"(r3) : "r"(addr))
#define LDSM_X4T(r0,r1,r2,r3, addr) \
    asm volatile("ldmatrix.sync.aligned.m8n8.x4.trans.shared.b16 {%0,%1,%2,%3}, [%4];" \
        : "=r"(r0),"=r"(r1),"=r"(r2),"=r"(r3) : "r"(addr))

#define MMA_F16(acc, a0,a1,a2,a3, b0,b1) \
    asm volatile("mma.sync.aligned.m16n8k16.row.col.f32.f16.f16.f32 " \
        "{%0,%1,%2,%3}, {%4,%5,%6,%7}, {%8,%9}, {%0,%1,%2,%3};" \
        : "+f"((acc)[0]), "+f"((acc)[1]), "+f"((acc)[2]), "+f"((acc)[3]) \
        : "r"(a0), "r"(a1), "r"(a2), "r"(a3), "r"(b0), "r"(b1))

__device__ __forceinline__ uint32_t pack_h2(float lo, float hi) {
    __half2 h = __floats2half2_rn(lo, hi);
    return *(uint32_t*)&h;
}
__device__ __forceinline__ float tanh_fast(float x) {
    float y;
    asm("tanh.approx.f32 %0, %1;" : "=f"(y) : "f"(x));
    return y;
}
__device__ __forceinline__ float gelu_f(float x) {
    float u = 0.7978845608028654f * (x + 0.044715f * x * x * x);
    return 0.5f * x * (1.0f + tanh_fast(u));
}

// ========== one-shot weight conversion, all 6 matrices ======================
#define SEG (DD*DD/2)          // 524288 half2 per DxD matrix
#define SEGF (DD*DFF/2)        // 2097152 half2 per DxDFF matrix
__global__ __launch_bounds__(256)
void cvt_all(const float* __restrict__ Wq, const float* __restrict__ Wk,
             const float* __restrict__ Wv, const float* __restrict__ Wo,
             const float* __restrict__ W1, const float* __restrict__ W2,
             __half* __restrict__ wqkv, __half* __restrict__ wo,
             __half* __restrict__ w1,   __half* __restrict__ w2)
{
    int i = blockIdx.x * 256 + threadIdx.x;
    const float2* src;
    __half2* dst;
    if (i < 3*SEG) {                       // Wq|Wk|Wv -> wqkv (strided concat)
        int s = i / SEG, j = i - s * SEG;
        src = (const float2*)(s == 0 ? Wq : s == 1 ? Wk : Wv) + j;
        int r = j / (DD/2), c = j - r * (DD/2);
        dst = (__half2*)wqkv + (size_t)r * (QST/2) + s * (DD/2) + c;
    } else if (i < 4*SEG) {
        int j = i - 3*SEG;
        src = (const float2*)Wo + j;  dst = (__half2*)wo + j;
    } else if (i < 4*SEG + SEGF) {
        int j = i - 4*SEG;
        src = (const float2*)W1 + j;  dst = (__half2*)w1 + j;
    } else {
        int j = i - 4*SEG - SEGF;
        src = (const float2*)W2 + j;  dst = (__half2*)w2 + j;
    }
    float2 v = *src;
    *dst = __floats2half2_rn(v.x, v.y);
}
#define CVT_BLOCKS ((4*SEG + 2*SEGF)/256)  // 24576

// ======================= LayerNorm (fp32 in, fp16 out) ======================
__global__ __launch_bounds__(256)
void ln_kernel(const float* __restrict__ x, const float* __restrict__ scale,
               const float* __restrict__ shift, __half* __restrict__ out)
{
    int row = blockIdx.x;
    const float* xr = x + (size_t)row * DD;
    __half* orow = out + (size_t)row * DD;
    int t = threadIdx.x;

    float v0 = xr[t], v1 = xr[t+256], v2 = xr[t+512], v3 = xr[t+768];
    float s  = v0+v1+v2+v3;
    float sq = v0*v0+v1*v1+v2*v2+v3*v3;

    __shared__ float red[2][256];
    red[0][t]=s; red[1][t]=sq; __syncthreads();
    for (int off=128; off>0; off>>=1) {
        if (t<off){ red[0][t]+=red[0][t+off]; red[1][t]+=red[1][t+off]; }
        __syncthreads();
    }
    float mean = red[0][0] * (1.0f/DD);
    float var  = red[1][0] * (1.0f/DD) - mean*mean;
    float inv  = rsqrtf(var + 1e-8f);

    orow[t    ] = __float2half_rn(scale[t    ]*(v0-mean)*inv + shift[t    ]);
    orow[t+256] = __float2half_rn(scale[t+256]*(v1-mean)*inv + shift[t+256]);
    orow[t+512] = __float2half_rn(scale[t+512]*(v2-mean)*inv + shift[t+512]);
    orow[t+768] = __float2half_rn(scale[t+768]*(v3-mean)*inv + shift[t+768]);
}

// ================= fp16 mma GEMM, 3-stage cp.async, warp tile 64x64 =========
#define AS_H 40
#define BS_H 136
#define SA_BYTES (128*AS_H*2)
#define SB_BYTES (32*BS_H*2)
#define STG_BYTES (SA_BYTES+SB_BYTES)
#define GEMM_SMEM (3*STG_BYTES)          // 56832

template<int EPI, int OUTH>
__global__ __launch_bounds__(128, 2)
void tgemm(const __half* __restrict__ A, const __half* __restrict__ W,
           const float* __restrict__ bias, const float* __restrict__ res,
           void* __restrict__ C, int N, int K)
{
    extern __shared__ char smem[];
    const uint32_t sb = smem_u32(smem);
    const int tid  = threadIdx.x;
    const int wid  = tid >> 5, lane = tid & 31;
    const int g    = lane >> 2, tg = lane & 3;
    const int wm   = (wid >> 1) * 64, wn = (wid & 1) * 64;
    const int brow = blockIdx.y * 128, bcol = blockIdx.x * 128;

    float acc[4][8][4];
    #pragma unroll
    for (int mi=0;mi<4;mi++)
        #pragma unroll
        for (int ni=0;ni<8;ni++)
            #pragma unroll
            for (int e=0;e<4;e++) acc[mi][ni][e]=0.f;

    auto stage = [&](int c, int buf) {
        uint32_t base = sb + buf * STG_BYTES;
        int k0 = c * 32;
        #pragma unroll
        for (int it = 0; it < 4; it++) {
            int idx = it * 128 + tid;
            int row = idx >> 2, c8 = (idx & 3) * 8;
            cp_async16(base + (uint32_t)(row * AS_H + c8) * 2,
                       A + (size_t)(brow + row) * K + k0 + c8);
        }
        #pragma unroll
        for (int it = 0; it < 4; it++) {
            int idx = it * 128 + tid;
            int row = idx >> 4, c8 = (idx & 15) * 8;
            cp_async16(base + SA_BYTES + (uint32_t)(row * BS_H + c8) * 2,
                       W + (size_t)(k0 + row) * N + bcol + c8);
        }
        CP_COMMIT();
    };

    const uint32_t aoff = (uint32_t)((wm + (lane & 15)) * AS_H + 8 * (lane >> 4)) * 2;
    const uint32_t boff = (uint32_t)(((lane & 7) + 8 * ((lane >> 3) & 1)) * BS_H
                                     + wn + 8 * (lane >> 4)) * 2;

    const int nch = K / 32;
    stage(0, 0);
    stage(1, 1);
    for (int c = 0; c < nch; c++) {
        if (c + 2 < nch)      { stage(c + 2, (c + 2) % 3); CP_WAIT(2); }
        else if (c + 1 < nch) { CP_WAIT(1); }
        else                  { CP_WAIT(0); }
        __syncthreads();
        uint32_t sbuf = sb + (c % 3) * STG_BYTES;

        #pragma unroll
        for (int kb = 0; kb < 32; kb += 16) {
            uint32_t a[4][4];
            #pragma unroll
            for (int mi = 0; mi < 4; mi++)
                LDSM_X4(a[mi][0], a[mi][1], a[mi][2], a[mi][3],
                        sbuf + aoff + (uint32_t)(mi * 16 * AS_H + kb) * 2);
            #pragma unroll
            for (int np = 0; np < 4; np++) {
                uint32_t t0,t1,t2,t3;
                LDSM_X4T(t0,t1,t2,t3,
                         sbuf + SA_BYTES + boff + (uint32_t)(kb * BS_H + np * 16) * 2);
                #pragma unroll
                for (int mi = 0; mi < 4; mi++) {
                    MMA_F16(acc[mi][2*np],   a[mi][0],a[mi][1],a[mi][2],a[mi][3], t0,t1);
                    MMA_F16(acc[mi][2*np+1], a[mi][0],a[mi][1],a[mi][2],a[mi][3], t2,t3);
                }
            }
        }
        __syncthreads();
    }

    #pragma unroll
    for (int mi = 0; mi < 4; mi++) {
        int r0 = brow + wm + mi * 16 + g;
        #pragma unroll
        for (int ni = 0; ni < 8; ni++) {
            int c = bcol + wn + ni * 8 + 2 * tg;
            float v0 = acc[mi][ni][0], v1 = acc[mi][ni][1];
            float v2 = acc[mi][ni][2], v3 = acc[mi][ni][3];
            if (EPI == 1) {
                float b0 = bias[c], b1 = bias[c+1];
                const float* R0 = res + (size_t)r0 * N + c;
                const float* R1 = res + (size_t)(r0+8) * N + c;
                v0 += b0 + R0[0]; v1 += b1 + R0[1];
                v2 += b0 + R1[0]; v3 += b1 + R1[1];
            }
            if (EPI == 2) {
                float b0 = bias[c], b1 = bias[c+1];
                v0 = gelu_f(v0 + b0); v1 = gelu_f(v1 + b1);
                v2 = gelu_f(v2 + b0); v3 = gelu_f(v3 + b1);
            }
            if (OUTH) {
                __half* Ch = (__half*)C;
                *(__half2*)(Ch + (size_t)r0 * N + c)     = __floats2half2_rn(v0, v1);
                *(__half2*)(Ch + (size_t)(r0+8) * N + c) = __floats2half2_rn(v2, v3);
            } else {
                float* Cf = (float*)C;
                *(float2*)(Cf + (size_t)r0 * N + c)     = make_float2(v0, v1);
                *(float2*)(Cf + (size_t)(r0+8) * N + c) = make_float2(v2, v3);
            }
        }
    }
}

// ============ fp16 tensor-core causal flash attention (register P) ==========
// 256 thr (8 warps), Q tile 128 rows, K/V tiles 64 keys, cp.async 2-stage.
// P stays in registers: S accumulator fragments repacked as mma A-fragments.
#define AQ_H 72
#define ATT_Q_OFF 0
#define ATT_K_OFF (128*AQ_H)
#define ATT_V_OFF (ATT_K_OFF + 2*64*AQ_H)
#define ATT_SMEM  ((ATT_V_OFF + 2*64*AQ_H)*2)   // 55296 bytes

__global__ __launch_bounds__(256, 2)
void attn_kernel(const __half* __restrict__ QKV, __half* __restrict__ O)
{
    extern __shared__ __half sh[];
    const uint32_t sb = smem_u32(sh);

    const int qt = blockIdx.x, bh = blockIdx.y;
    const int b = bh >> 4, hh = bh & 15;
    const int tid = threadIdx.x, w = tid >> 5, lane = tid & 31;
    const int g = lane >> 2, tg = lane & 3;

    {
        const __half* Qg = QKV + ((size_t)(b*SS + qt*128))*QST + hh*64;
        #pragma unroll
        for (int it = 0; it < 4; it++) {
            int idx = it * 256 + tid;
            int row = idx >> 3, c8 = (idx & 7) * 8;
            cp_async16(sb + (uint32_t)(ATT_Q_OFF + row * AQ_H + c8) * 2,
                       Qg + (size_t)row * QST + c8);
        }
    }
    auto loadKV = [&](int kt, int buf) {
        const __half* Kg = QKV + ((size_t)(b*SS + kt*64))*QST + DD   + hh*64;
        const __half* Vg = QKV + ((size_t)(b*SS + kt*64))*QST + 2*DD + hh*64;
        uint32_t kbase = sb + (uint32_t)(ATT_K_OFF + buf * 64 * AQ_H) * 2;
        uint32_t vbase = sb + (uint32_t)(ATT_V_OFF + buf * 64 * AQ_H) * 2;
        #pragma unroll
        for (int it = 0; it < 2; it++) {
            int idx = it * 256 + tid;
            int row = idx >> 3, c8 = (idx & 7) * 8;
            cp_async16(kbase + (uint32_t)(row * AQ_H + c8) * 2, Kg + (size_t)row * QST + c8);
            cp_async16(vbase + (uint32_t)(row * AQ_H + c8) * 2, Vg + (size_t)row * QST + c8);
        }
        CP_COMMIT();
    };

    float oacc[8][4];
    #pragma unroll
    for (int ni=0;ni<8;ni++)
        #pragma unroll
        for (int e=0;e<4;e++) oacc[ni][e]=0.f;
    float m0 = -INFINITY, m1 = -INFINITY, l0 = 0.f, l1 = 0.f;

    const uint32_t qoff = (uint32_t)((w*16 + (lane & 15)) * AQ_H + 8 * (lane >> 4)) * 2;
    const uint32_t koff = (uint32_t)(((lane & 7) + 8 * (lane >> 4)) * AQ_H
                                     + 8 * ((lane >> 3) & 1)) * 2;
    const uint32_t voff = (uint32_t)(((lane & 7) + 8 * ((lane >> 3) & 1)) * AQ_H
                                     + 8 * (lane >> 4)) * 2;

    loadKV(0, 0);
    const int nkt = 2 * qt + 2;
    for (int kt = 0; kt < nkt; kt++) {
        int buf = kt & 1;
        if (kt + 1 < nkt) { loadKV(kt + 1, buf ^ 1); CP_WAIT(1); }
        else              { CP_WAIT(0); }
        __syncthreads();

        uint32_t kb_sm = sb + (uint32_t)(ATT_K_OFF + buf * 64 * AQ_H) * 2;
        uint32_t vb_sm = sb + (uint32_t)(ATT_V_OFF + buf * 64 * AQ_H) * 2;

        // S = Q K^T
        float sacc[8][4];
        #pragma unroll
        for (int ni=0;ni<8;ni++)
            #pragma unroll
            for (int e=0;e<4;e++) sacc[ni][e]=0.f;

        #pragma unroll
        for (int kb = 0; kb < 64; kb += 16) {
            uint32_t a0,a1,a2,a3;
            LDSM_X4(a0,a1,a2,a3, sb + (uint32_t)(ATT_Q_OFF)*2 + qoff + (uint32_t)kb * 2);
            #pragma unroll
            for (int np = 0; np < 4; np++) {
                uint32_t t0,t1,t2,t3;
                LDSM_X4(t0,t1,t2,t3, kb_sm + koff + (uint32_t)(np * 16 * AQ_H + kb) * 2);
                MMA_F16(sacc[2*np],   a0,a1,a2,a3, t0,t1);
                MMA_F16(sacc[2*np+1], a0,a1,a2,a3, t2,t3);
            }
        }

        // scale + causal mask
        const bool needMask = (kt * 64 + 63) > (qt * 128 + w * 16);
        const int qg0 = qt*128 + w*16 + g, qg1 = qg0 + 8;
        #pragma unroll
        for (int ni = 0; ni < 8; ni++) {
            int key0 = kt*64 + ni*8 + 2*tg;
            #pragma unroll
            for (int e = 0; e < 4; e++) {
                float s = sacc[ni][e] * 0.125f;
                if (needMask) {
                    int key = key0 + (e & 1);
                    int qr  = (e >= 2) ? qg1 : qg0;
                    if (key > qr) s = -INFINITY;
                }
                sacc[ni][e] = s;
            }
        }

        // online softmax
        float rx0 = -INFINITY, rx1 = -INFINITY;
        #pragma unroll
        for (int ni = 0; ni < 8; ni++) {
            rx0 = fmaxf(rx0, fmaxf(sacc[ni][0], sacc[ni][1]));
            rx1 = fmaxf(rx1, fmaxf(sacc[ni][2], sacc[ni][3]));
        }
        rx0 = fmaxf(rx0, __shfl_xor_sync(0xffffffff, rx0, 1));
        rx0 = fmaxf(rx0, __shfl_xor_sync(0xffffffff, rx0, 2));
        rx1 = fmaxf(rx1, __shfl_xor_sync(0xffffffff, rx1, 1));
        rx1 = fmaxf(rx1, __shfl_xor_sync(0xffffffff, rx1, 2));
        float mn0 = fmaxf(m0, rx0), mn1 = fmaxf(m1, rx1);
        float c0 = __expf(m0 - mn0), c1 = __expf(m1 - mn1);

        // exp -> register-resident P as mma A-fragments
        uint32_t aP[4][4];
        float rs0 = 0.f, rs1 = 0.f;
        #pragma unroll
        for (int j = 0; j < 4; j++) {
            int n0 = 2*j, n1 = 2*j + 1;
            float p00 = __expf(sacc[n0][0] - mn0);
            float p01 = __expf(sacc[n0][1] - mn0);
            float p02 = __expf(sacc[n0][2] - mn1);
            float p03 = __expf(sacc[n0][3] - mn1);
            float p10 = __expf(sacc[n1][0] - mn0);
            float p11 = __expf(sacc[n1][1] - mn0);
            float p12 = __expf(sacc[n1][2] - mn1);
            float p13 = __expf(sacc[n1][3] - mn1);
            rs0 += p00 + p01 + p10 + p11;
            rs1 += p02 + p03 + p12 + p13;
            aP[j][0] = pack_h2(p00, p01);   // (row g,   k 2tg..)
            aP[j][1] = pack_h2(p02, p03);   // (row g+8, k 2tg..)
            aP[j][2] = pack_h2(p10, p11);   // (row g,   k 2tg+8..)
            aP[j][3] = pack_h2(p12, p13);   // (row g+8, k 2tg+8..)
        }
        rs0 += __shfl_xor_sync(0xffffffff, rs0, 1);
        rs0 += __shfl_xor_sync(0xffffffff, rs0, 2);
        rs1 += __shfl_xor_sync(0xffffffff, rs1, 1);
        rs1 += __shfl_xor_sync(0xffffffff, rs1, 2);
        l0 = l0 * c0 + rs0;  l1 = l1 * c1 + rs1;
        m0 = mn0;  m1 = mn1;

        #pragma unroll
        for (int ni = 0; ni < 8; ni++) {
            oacc[ni][0] *= c0; oacc[ni][1] *= c0;
            oacc[ni][2] *= c1; oacc[ni][3] *= c1;
        }

        // O += P V  (P from registers, V via trans ldmatrix)
        #pragma unroll
        for (int j = 0; j < 4; j++) {
            #pragma unroll
            for (int np = 0; np < 4; np++) {
                uint32_t t0,t1,t2,t3;
                LDSM_X4T(t0,t1,t2,t3, vb_sm + voff + (uint32_t)(j * 16 * AQ_H + np * 16) * 2);
                MMA_F16(oacc[2*np],   aP[j][0],aP[j][1],aP[j][2],aP[j][3], t0,t1);
                MMA_F16(oacc[2*np+1], aP[j][0],aP[j][1],aP[j][2],aP[j][3], t2,t3);
            }
        }
        __syncthreads();
    }

    float i0 = 1.f / l0, i1 = 1.f / l1;
    #pragma unroll
    for (int ni = 0; ni < 8; ni++) {
        int c = hh*64 + ni*8 + 2*tg;
        size_t go = ((size_t)(b*SS + qt*128 + w*16 + g)) * DD + c;
        *(__half2*)(O + go)        = __floats2half2_rn(oacc[ni][0]*i0, oacc[ni][1]*i0);
        *(__half2*)(O + go + 8*DD) = __floats2half2_rn(oacc[ni][2]*i1, oacc[ni][3]*i1);
    }
}

// ======================= launcher ===========================================
extern "C" void kernel_launch(void* const* d_in, const int* in_sizes, int n_in,
                              void* d_out, int out_size)
{
    const float* x    = (const float*)d_in[0];
    const float* Wq   = (const float*)d_in[1];
    const float* Wk   = (const float*)d_in[2];
    const float* Wv   = (const float*)d_in[3];
    const float* Wo   = (const float*)d_in[4];
    const float* bo   = (const float*)d_in[5];
    const float* W1   = (const float*)d_in[6];
    const float* b1   = (const float*)d_in[7];
    const float* W2   = (const float*)d_in[8];
    const float* b2   = (const float*)d_in[9];
    const float* ln1s = (const float*)d_in[10];
    const float* ln1b = (const float*)d_in[11];
    const float* ln2s = (const float*)d_in[12];
    const float* ln2b = (const float*)d_in[13];
    float* out = (float*)d_out;

    __half *h,*qkv,*ctx,*ff,*wqkv,*wo,*w1,*w2;
    float *x1;
    cudaGetSymbolAddress((void**)&h,    g_h);
    cudaGetSymbolAddress((void**)&qkv,  g_qkv);
    cudaGetSymbolAddress((void**)&ctx,  g_ctx);
    cudaGetSymbolAddress((void**)&x1,   g_x1);
    cudaGetSymbolAddress((void**)&ff,   g_ff);
    cudaGetSymbolAddress((void**)&wqkv, g_wqkv);
    cudaGetSymbolAddress((void**)&wo,   g_wo);
    cudaGetSymbolAddress((void**)&w1,   g_w1);
    cudaGetSymbolAddress((void**)&w2,   g_w2);

    cudaFuncSetAttribute(tgemm<0,1>, cudaFuncAttributeMaxDynamicSharedMemorySize, GEMM_SMEM);
    cudaFuncSetAttribute(tgemm<1,0>, cudaFuncAttributeMaxDynamicSharedMemorySize, GEMM_SMEM);
    cudaFuncSetAttribute(tgemm<2,1>, cudaFuncAttributeMaxDynamicSharedMemorySize, GEMM_SMEM);
    cudaFuncSetAttribute(attn_kernel, cudaFuncAttributeMaxDynamicSharedMemorySize, ATT_SMEM);

    cvt_all<<<CVT_BLOCKS, 256>>>(Wq, Wk, Wv, Wo, W1, W2, wqkv, wo, w1, w2);

    dim3 gQKV(QST/128, ROWS/128);  // (24, 64)
    dim3 gD  (DD/128,  ROWS/128);  // (8, 64)
    dim3 gFF (DFF/128, ROWS/128);  // (32, 64)

    ln_kernel<<<ROWS, 256>>>(x, ln1s, ln1b, h);
    tgemm<0,1><<<gQKV, 128, GEMM_SMEM>>>(h, wqkv, nullptr, nullptr, qkv, QST, DD);
    attn_kernel<<<dim3(SS/128, BB*HH), 256, ATT_SMEM>>>(qkv, ctx);
    tgemm<1,0><<<gD, 128, GEMM_SMEM>>>(ctx, wo, bo, x, x1, DD, DD);
    ln_kernel<<<ROWS, 256>>>(x1, ln2s, ln2b, h);
    tgemm<2,1><<<gFF, 128, GEMM_SMEM>>>(h, w1, b1, nullptr, ff, DFF, DD);
    tgemm<1,0><<<gD, 128, GEMM_SMEM>>>(ff, w2, b2, x1, out, DD, DFF);
}